// round 2
// baseline (speedup 1.0000x reference)
#include <cuda_runtime.h>
#include <cstdint>
#include <cstddef>

#define DEV_INLINE __device__ __forceinline__

constexpr int Bb  = 2;
constexpr int S   = 2048;
constexpr int H   = 32;
constexpr int HK  = 8;
constexpr int HD  = 64;
constexpr int D   = H * HD;    // 2048
constexpr int Dkv = HK * HD;   // 512
constexpr int M   = Bb * S;    // 4096
constexpr int NPAIR = HD / 2;  // 32

__device__ float  g_Q[M * D];
__device__ float  g_K[M * Dkv];
__device__ float  g_V[M * Dkv];
__device__ float  g_Z[M * D];
__device__ float2 g_rope[S * NPAIR];

// ---------------------------------------------------------------- tf32 utils
DEV_INLINE uint32_t f2tf(float x) {
    uint32_t r;
    asm("cvt.rna.tf32.f32 %0, %1;" : "=r"(r) : "f"(x));
    return r;
}
DEV_INLINE void split1(float v, uint32_t& h, uint32_t& l) {
    h = f2tf(v);
    l = f2tf(v - __uint_as_float(h));
}
DEV_INLINE void split_store(uint32_t* Sh, uint32_t* Sl, int base, float4 v) {
    uint4 hh, ll;
    split1(v.x, hh.x, ll.x);
    split1(v.y, hh.y, ll.y);
    split1(v.z, hh.z, ll.z);
    split1(v.w, hh.w, ll.w);
    *(uint4*)&Sh[base] = hh;
    *(uint4*)&Sl[base] = ll;
}
DEV_INLINE void mma_tf32(float* c, const uint32_t* a, uint32_t b0, uint32_t b1) {
    asm volatile(
        "mma.sync.aligned.m16n8k8.row.col.f32.tf32.tf32.f32 "
        "{%0,%1,%2,%3}, {%4,%5,%6,%7}, {%8,%9}, {%0,%1,%2,%3};\n"
        : "+f"(c[0]), "+f"(c[1]), "+f"(c[2]), "+f"(c[3])
        : "r"(a[0]), "r"(a[1]), "r"(a[2]), "r"(a[3]), "r"(b0), "r"(b1));
}

// ---------------------------------------------------------------- rope table
__global__ void rope_table_kernel() {
    int idx = blockIdx.x * blockDim.x + threadIdx.x;
    if (idx >= S * NPAIR) return;
    int s = idx / NPAIR, p = idx % NPAIR;
    float pf   = (float)pow(10000.0, (double)(2 * p) / 64.0);
    float freq = 1.0f / pf;
    float t    = (float)s * 6.2831853071795864769f;
    float ang  = t * freq;
    double ad  = (double)ang;
    g_rope[idx] = make_float2((float)cos(ad), (float)sin(ad));
}

// ---------------------------------------------------------------- GEMM tile
// C[m0:+128, n0:+128] = A[.,2048] @ W[.,2048]^T, split-tf32, optional RoPE.
constexpr int GP = 36;

DEV_INLINE void gemm_tile(const float* __restrict__ A, const float* __restrict__ W,
                          float* __restrict__ C, int n0, int m0, int ldc, int rope,
                          uint32_t* sm) {
    uint32_t* Ah = sm;
    uint32_t* Al = Ah + 128 * GP;
    uint32_t* Bh = Al + 128 * GP;
    uint32_t* Bl = Bh + 128 * GP;

    const int t    = threadIdx.x;
    const int lr   = t >> 3;
    const int lc   = (t & 7) * 4;
    const int wid  = t >> 5;
    const int lane = t & 31;
    const int wm   = wid >> 1;
    const int wn   = wid & 1;
    const int r    = lane >> 2;
    const int q    = lane & 3;

    float acc[2][8][4];
#pragma unroll
    for (int a = 0; a < 2; a++)
#pragma unroll
        for (int b = 0; b < 8; b++)
#pragma unroll
            for (int c = 0; c < 4; c++) acc[a][b][c] = 0.f;

    for (int kt = 0; kt < 2048; kt += 32) {
#pragma unroll
        for (int i = 0; i < 4; i++) {
            int rw = lr + i * 32;
            float4 va = *(const float4*)&A[(size_t)(m0 + rw) * 2048 + kt + lc];
            float4 vb = *(const float4*)&W[(size_t)(n0 + rw) * 2048 + kt + lc];
            split_store(Ah, Al, rw * GP + lc, va);
            split_store(Bh, Bl, rw * GP + lc, vb);
        }
        __syncthreads();
#pragma unroll
        for (int ks = 0; ks < 4; ks++) {
            uint32_t ah[2][4], al[2][4];
#pragma unroll
            for (int mt = 0; mt < 2; mt++) {
                int rb = wm * 32 + mt * 16;
                int o  = (rb + r) * GP + ks * 8 + q;
                int o8 = o + 8 * GP;
                ah[mt][0] = Ah[o];     ah[mt][1] = Ah[o8];
                ah[mt][2] = Ah[o + 4]; ah[mt][3] = Ah[o8 + 4];
                al[mt][0] = Al[o];     al[mt][1] = Al[o8];
                al[mt][2] = Al[o + 4]; al[mt][3] = Al[o8 + 4];
            }
#pragma unroll
            for (int nt = 0; nt < 8; nt++) {
                int o = (wn * 64 + nt * 8 + r) * GP + ks * 8 + q;
                uint32_t bh0 = Bh[o], bh1 = Bh[o + 4];
                uint32_t bl0 = Bl[o], bl1 = Bl[o + 4];
#pragma unroll
                for (int mt = 0; mt < 2; mt++) {
                    mma_tf32(acc[mt][nt], ah[mt], bh0, bh1);
                    mma_tf32(acc[mt][nt], al[mt], bh0, bh1);
                    mma_tf32(acc[mt][nt], ah[mt], bl0, bl1);
                }
            }
        }
        __syncthreads();
    }

#pragma unroll
    for (int mt = 0; mt < 2; mt++) {
        int row0 = m0 + wm * 32 + mt * 16 + r;
#pragma unroll
        for (int nt = 0; nt < 8; nt++) {
            int gc = n0 + wn * 64 + nt * 8 + 2 * q;
            float v0 = acc[mt][nt][0], v1 = acc[mt][nt][1];
            float v2 = acc[mt][nt][2], v3 = acc[mt][nt][3];
            if (rope) {
                int p = (gc & 63) >> 1;
                float2 cs0 = g_rope[(row0 & (S - 1)) * NPAIR + p];
                float2 cs1 = g_rope[((row0 + 8) & (S - 1)) * NPAIR + p];
                float r0 = v0 * cs0.x - v1 * cs0.y;
                float i0 = v0 * cs0.y + v1 * cs0.x;
                float r1 = v2 * cs1.x - v3 * cs1.y;
                float i1 = v2 * cs1.y + v3 * cs1.x;
                v0 = r0; v1 = i0; v2 = r1; v3 = i1;
            }
            *(float2*)&C[(size_t)row0 * ldc + gc]       = make_float2(v0, v1);
            *(float2*)&C[(size_t)(row0 + 8) * ldc + gc] = make_float2(v2, v3);
        }
    }
}

constexpr int GEMM_SMEM = 4 * 128 * GP * 4;  // 73728

__global__ void __launch_bounds__(256) qkv_kernel(const float* __restrict__ x,
                                                  const float* __restrict__ Wq,
                                                  const float* __restrict__ Wk,
                                                  const float* __restrict__ Wv) {
    extern __shared__ char smraw[];
    int bx = blockIdx.x, m0 = blockIdx.y * 128;
    const float* Wsel;
    float* Csel;
    int n0, ldc, rope;
    if (bx < 16)      { Wsel = Wq; Csel = g_Q; n0 = bx * 128;        ldc = D;   rope = 1; }
    else if (bx < 20) { Wsel = Wk; Csel = g_K; n0 = (bx - 16) * 128; ldc = Dkv; rope = 1; }
    else              { Wsel = Wv; Csel = g_V; n0 = (bx - 20) * 128; ldc = Dkv; rope = 0; }
    gemm_tile(x, Wsel, Csel, n0, m0, ldc, rope, (uint32_t*)smraw);
}

__global__ void __launch_bounds__(256) out_kernel(const float* __restrict__ Wo,
                                                  float* __restrict__ out) {
    extern __shared__ char smraw[];
    gemm_tile(g_Z, Wo, out, blockIdx.x * 128, blockIdx.y * 128, D, 0, (uint32_t*)smraw);
}

// ---------------------------------------------------------------- attention
constexpr int QP = 68, PP = 36, KP = 68, VP = 72;
constexpr int ATTN_SMEM = (128 * QP + 128 * PP + 2 * 32 * KP + 2 * 32 * VP) * 4; // 89088

__global__ void __launch_bounds__(256) attn_kernel() {
    extern __shared__ char smraw[];
    float*    Qs = (float*)smraw;
    uint32_t* Ps = (uint32_t*)(smraw + 128 * QP * 4);
    uint32_t* Kh = (uint32_t*)(smraw + (128 * QP + 128 * PP) * 4);
    uint32_t* Kl = Kh + 32 * KP;
    uint32_t* Vh = Kl + 32 * KP;
    uint32_t* Vl = Vh + 32 * VP;

    const int t = threadIdx.x, wid = t >> 5, lane = t & 31;
    const int r = lane >> 2, q = lane & 3;
    const int bh = blockIdx.y, b = bh >> 5, h = bh & 31, kvh = h >> 2;
    const int q0 = blockIdx.x * 128, w16 = wid * 16;

    const float* Qg = g_Q + (size_t)(b * S + q0) * D + h * HD;
    const float* Kg = g_K + (size_t)(b * S) * Dkv + kvh * HD;
    const float* Vg = g_V + (size_t)(b * S) * Dkv + kvh * HD;

#pragma unroll
    for (int i = 0; i < 8; i++) {
        int e = t + i * 256;
        int row = e >> 4, c4 = (e & 15) * 4;
        float4 v = *(const float4*)&Qg[(size_t)row * D + c4];
        v.x *= 0.125f; v.y *= 0.125f; v.z *= 0.125f; v.w *= 0.125f;
        *(float4*)&Qs[row * QP + c4] = v;
    }

    float oacc[8][4];
#pragma unroll
    for (int nt = 0; nt < 8; nt++)
#pragma unroll
        for (int c = 0; c < 4; c++) oacc[nt][c] = 0.f;
    float m0v = -1e30f, m1v = -1e30f, l0v = 0.f, l1v = 0.f;

    const int nkt = q0 / 32 + 4;
    for (int kt = 0; kt < nkt; kt++) {
        int k0 = kt * 32;
        __syncthreads();
#pragma unroll
        for (int i = 0; i < 2; i++) {
            int e = t + i * 256;
            int row = e >> 4, c4 = (e & 15) * 4;
            float4 kv = *(const float4*)&Kg[(size_t)(k0 + row) * Dkv + c4];
            float4 vv = *(const float4*)&Vg[(size_t)(k0 + row) * Dkv + c4];
            split_store(Kh, Kl, row * KP + c4, kv);
            split_store(Vh, Vl, row * VP + c4, vv);
        }
        __syncthreads();
        if (k0 > q0 + w16 + 15) continue;  // warp-uniform causal skip (after both barriers)

        float sacc[4][4];
#pragma unroll
        for (int nt = 0; nt < 4; nt++)
#pragma unroll
            for (int c = 0; c < 4; c++) sacc[nt][c] = 0.f;

#pragma unroll
        for (int ks = 0; ks < 8; ks++) {
            uint32_t ah[4], al[4];
            int o = (w16 + r) * QP + ks * 8 + q;
            split1(Qs[o],            ah[0], al[0]);
            split1(Qs[o + 8 * QP],   ah[1], al[1]);
            split1(Qs[o + 4],        ah[2], al[2]);
            split1(Qs[o + 8 * QP + 4], ah[3], al[3]);
#pragma unroll
            for (int nt = 0; nt < 4; nt++) {
                int ob = (nt * 8 + r) * KP + ks * 8 + q;
                uint32_t bh0 = Kh[ob], bh1 = Kh[ob + 4];
                uint32_t bl0 = Kl[ob], bl1 = Kl[ob + 4];
                mma_tf32(sacc[nt], ah, bh0, bh1);
                mma_tf32(sacc[nt], al, bh0, bh1);
                mma_tf32(sacc[nt], ah, bl0, bl1);
            }
        }

        int qr0 = q0 + w16 + r, qr1 = qr0 + 8;
        if (k0 + 31 > q0 + w16) {
#pragma unroll
            for (int nt = 0; nt < 4; nt++) {
                int kc = k0 + nt * 8 + 2 * q;
                if (kc     > qr0) sacc[nt][0] = -1e30f;
                if (kc + 1 > qr0) sacc[nt][1] = -1e30f;
                if (kc     > qr1) sacc[nt][2] = -1e30f;
                if (kc + 1 > qr1) sacc[nt][3] = -1e30f;
            }
        }

        float rm0 = -1e30f, rm1 = -1e30f;
#pragma unroll
        for (int nt = 0; nt < 4; nt++) {
            rm0 = fmaxf(rm0, fmaxf(sacc[nt][0], sacc[nt][1]));
            rm1 = fmaxf(rm1, fmaxf(sacc[nt][2], sacc[nt][3]));
        }
        rm0 = fmaxf(rm0, __shfl_xor_sync(~0u, rm0, 1));
        rm0 = fmaxf(rm0, __shfl_xor_sync(~0u, rm0, 2));
        rm1 = fmaxf(rm1, __shfl_xor_sync(~0u, rm1, 1));
        rm1 = fmaxf(rm1, __shfl_xor_sync(~0u, rm1, 2));

        float mn0 = fmaxf(m0v, rm0), mn1 = fmaxf(m1v, rm1);
        float a0 = __expf(m0v - mn0), a1 = __expf(m1v - mn1);
        m0v = mn0; m1v = mn1;

        float ps0 = 0.f, ps1 = 0.f;
#pragma unroll
        for (int nt = 0; nt < 4; nt++) {
            float p0 = __expf(sacc[nt][0] - mn0);
            float p1 = __expf(sacc[nt][1] - mn0);
            float p2 = __expf(sacc[nt][2] - mn1);
            float p3 = __expf(sacc[nt][3] - mn1);
            ps0 += p0 + p1; ps1 += p2 + p3;
            int ob = (w16 + r) * PP + nt * 8 + 2 * q;
            Ps[ob]            = f2tf(p0);
            Ps[ob + 1]        = f2tf(p1);
            Ps[ob + 8 * PP]     = f2tf(p2);
            Ps[ob + 8 * PP + 1] = f2tf(p3);
        }
        ps0 += __shfl_xor_sync(~0u, ps0, 1); ps0 += __shfl_xor_sync(~0u, ps0, 2);
        ps1 += __shfl_xor_sync(~0u, ps1, 1); ps1 += __shfl_xor_sync(~0u, ps1, 2);
        l0v = l0v * a0 + ps0;
        l1v = l1v * a1 + ps1;
#pragma unroll
        for (int nt = 0; nt < 8; nt++) {
            oacc[nt][0] *= a0; oacc[nt][1] *= a0;
            oacc[nt][2] *= a1; oacc[nt][3] *= a1;
        }
        __syncwarp();

#pragma unroll
        for (int ks = 0; ks < 4; ks++) {
            uint32_t pa[4];
            int o = (w16 + r) * PP + ks * 8 + q;
            pa[0] = Ps[o];     pa[1] = Ps[o + 8 * PP];
            pa[2] = Ps[o + 4]; pa[3] = Ps[o + 8 * PP + 4];
#pragma unroll
            for (int nt = 0; nt < 8; nt++) {
                int ob  = (ks * 8 + q) * VP + nt * 8 + r;
                int ob2 = (ks * 8 + q + 4) * VP + nt * 8 + r;
                mma_tf32(oacc[nt], pa, Vh[ob], Vh[ob2]);
                mma_tf32(oacc[nt], pa, Vl[ob], Vl[ob2]);
            }
        }
    }

    float inv0 = 1.f / l0v, inv1 = 1.f / l1v;
    float* Zg = g_Z + (size_t)(b * S + q0 + w16 + r) * D + h * HD;
#pragma unroll
    for (int nt = 0; nt < 8; nt++) {
        *(float2*)&Zg[nt * 8 + 2 * q] =
            make_float2(oacc[nt][0] * inv0, oacc[nt][1] * inv0);
        *(float2*)&Zg[(size_t)8 * D + nt * 8 + 2 * q] =
            make_float2(oacc[nt][2] * inv1, oacc[nt][3] * inv1);
    }
}

// ---------------------------------------------------------------- launch
extern "C" void kernel_launch(void* const* d_in, const int* in_sizes, int n_in,
                              void* d_out, int out_size) {
    const float* x  = (const float*)d_in[0];
    const float* Wq = (const float*)d_in[1];
    const float* Wk = (const float*)d_in[2];
    const float* Wv = (const float*)d_in[3];
    const float* Wo = (const float*)d_in[4];
    float* out = (float*)d_out;

    cudaFuncSetAttribute(qkv_kernel, cudaFuncAttributeMaxDynamicSharedMemorySize, GEMM_SMEM);
    cudaFuncSetAttribute(attn_kernel, cudaFuncAttributeMaxDynamicSharedMemorySize, ATTN_SMEM);
    cudaFuncSetAttribute(out_kernel, cudaFuncAttributeMaxDynamicSharedMemorySize, GEMM_SMEM);

    rope_table_kernel<<<(S * NPAIR + 255) / 256, 256>>>();
    qkv_kernel<<<dim3(24, 32), 256, GEMM_SMEM>>>(x, Wq, Wk, Wv);
    attn_kernel<<<dim3(16, 64), 256, ATTN_SMEM>>>();
    out_kernel<<<dim3(16, 32), 256, GEMM_SMEM>>>(Wo, out);
}

// round 3
// speedup vs baseline: 1.1995x; 1.1995x over previous
#include <cuda_runtime.h>
#include <cstdint>
#include <cstddef>

#define DEV_INLINE __device__ __forceinline__

constexpr int Bb  = 2;
constexpr int S   = 2048;
constexpr int H   = 32;
constexpr int HK  = 8;
constexpr int HD  = 64;
constexpr int D   = H * HD;    // 2048
constexpr int Dkv = HK * HD;   // 512
constexpr int M   = Bb * S;    // 4096
constexpr int NPAIR = HD / 2;  // 32

__device__ float  g_Q[M * D];
__device__ float  g_K[M * Dkv];
__device__ float  g_V[M * Dkv];
__device__ float  g_Z[M * D];
__device__ float2 g_rope[S * NPAIR];

// ---------------------------------------------------------------- tf32 utils
DEV_INLINE uint32_t f2tf(float x) {
    uint32_t r;
    asm("cvt.rna.tf32.f32 %0, %1;" : "=r"(r) : "f"(x));
    return r;
}
DEV_INLINE void split1(float v, uint32_t& h, uint32_t& l) {
    h = f2tf(v);
    l = f2tf(v - __uint_as_float(h));
}
DEV_INLINE void split_store(uint32_t* Sh, uint32_t* Sl, int base, float4 v) {
    uint4 hh, ll;
    split1(v.x, hh.x, ll.x);
    split1(v.y, hh.y, ll.y);
    split1(v.z, hh.z, ll.z);
    split1(v.w, hh.w, ll.w);
    *(uint4*)&Sh[base] = hh;
    *(uint4*)&Sl[base] = ll;
}
DEV_INLINE void tf_store(uint32_t* Sh, int base, float4 v) {
    uint4 hh;
    hh.x = f2tf(v.x); hh.y = f2tf(v.y); hh.z = f2tf(v.z); hh.w = f2tf(v.w);
    *(uint4*)&Sh[base] = hh;
}
DEV_INLINE void mma_tf32(float* c, const uint32_t* a, uint32_t b0, uint32_t b1) {
    asm volatile(
        "mma.sync.aligned.m16n8k8.row.col.f32.tf32.tf32.f32 "
        "{%0,%1,%2,%3}, {%4,%5,%6,%7}, {%8,%9}, {%0,%1,%2,%3};\n"
        : "+f"(c[0]), "+f"(c[1]), "+f"(c[2]), "+f"(c[3])
        : "r"(a[0]), "r"(a[1]), "r"(a[2]), "r"(a[3]), "r"(b0), "r"(b1));
}

// ---------------------------------------------------------------- rope table
__global__ void rope_table_kernel() {
    int idx = blockIdx.x * blockDim.x + threadIdx.x;
    if (idx >= S * NPAIR) return;
    int s = idx / NPAIR, p = idx % NPAIR;
    float pf   = (float)pow(10000.0, (double)(2 * p) / 64.0);
    float freq = 1.0f / pf;
    float t    = (float)s * 6.2831853071795864769f;
    float ang  = t * freq;
    double ad  = (double)ang;
    g_rope[idx] = make_float2((float)cos(ad), (float)sin(ad));
}

// ---------------------------------------------------------------- GEMM tile
// C[m0:+128, n0:+128] = A[.,2048] @ W[.,2048]^T.
// SPLIT=1: split-tf32 (3 MMAs, fp32-accurate). SPLIT=0: single tf32 (1 MMA).
// Software-pipelined: next K-tile prefetched into registers during MMA work.
constexpr int GP = 36;

template <int SPLIT>
DEV_INLINE void gemm_tile(const float* __restrict__ A, const float* __restrict__ W,
                          float* __restrict__ C, int n0, int m0, int ldc, int rope,
                          uint32_t* sm) {
    uint32_t* Ah = sm;
    uint32_t* Bh = Ah + 128 * GP;
    uint32_t* Al = Bh + 128 * GP;   // used only when SPLIT
    uint32_t* Bl = Al + 128 * GP;

    const int t    = threadIdx.x;
    const int lr   = t >> 3;
    const int lc   = (t & 7) * 4;
    const int wid  = t >> 5;
    const int lane = t & 31;
    const int wm   = wid >> 1;
    const int wn   = wid & 1;
    const int r    = lane >> 2;
    const int q    = lane & 3;

    float acc[2][8][4];
#pragma unroll
    for (int a = 0; a < 2; a++)
#pragma unroll
        for (int b = 0; b < 8; b++)
#pragma unroll
            for (int c = 0; c < 4; c++) acc[a][b][c] = 0.f;

    float4 pa[4], pb[4];
#pragma unroll
    for (int i = 0; i < 4; i++) {
        int rw = lr + i * 32;
        pa[i] = *(const float4*)&A[(size_t)(m0 + rw) * 2048 + lc];
        pb[i] = *(const float4*)&W[(size_t)(n0 + rw) * 2048 + lc];
    }

    for (int kt = 0; kt < 2048; kt += 32) {
#pragma unroll
        for (int i = 0; i < 4; i++) {
            int rw = lr + i * 32;
            if (SPLIT) {
                split_store(Ah, Al, rw * GP + lc, pa[i]);
                split_store(Bh, Bl, rw * GP + lc, pb[i]);
            } else {
                tf_store(Ah, rw * GP + lc, pa[i]);
                tf_store(Bh, rw * GP + lc, pb[i]);
            }
        }
        __syncthreads();
        if (kt + 32 < 2048) {
#pragma unroll
            for (int i = 0; i < 4; i++) {
                int rw = lr + i * 32;
                pa[i] = *(const float4*)&A[(size_t)(m0 + rw) * 2048 + kt + 32 + lc];
                pb[i] = *(const float4*)&W[(size_t)(n0 + rw) * 2048 + kt + 32 + lc];
            }
        }
#pragma unroll
        for (int ks = 0; ks < 4; ks++) {
            uint32_t ah[2][4], al[2][4];
#pragma unroll
            for (int mt = 0; mt < 2; mt++) {
                int rb = wm * 32 + mt * 16;
                int o  = (rb + r) * GP + ks * 8 + q;
                int o8 = o + 8 * GP;
                ah[mt][0] = Ah[o];     ah[mt][1] = Ah[o8];
                ah[mt][2] = Ah[o + 4]; ah[mt][3] = Ah[o8 + 4];
                if (SPLIT) {
                    al[mt][0] = Al[o];     al[mt][1] = Al[o8];
                    al[mt][2] = Al[o + 4]; al[mt][3] = Al[o8 + 4];
                }
            }
#pragma unroll
            for (int nt = 0; nt < 8; nt++) {
                int o = (wn * 64 + nt * 8 + r) * GP + ks * 8 + q;
                uint32_t bh0 = Bh[o], bh1 = Bh[o + 4];
#pragma unroll
                for (int mt = 0; mt < 2; mt++) {
                    mma_tf32(acc[mt][nt], ah[mt], bh0, bh1);
                    if (SPLIT) {
                        uint32_t bl0 = Bl[o], bl1 = Bl[o + 4];
                        mma_tf32(acc[mt][nt], al[mt], bh0, bh1);
                        mma_tf32(acc[mt][nt], ah[mt], bl0, bl1);
                    }
                }
            }
        }
        __syncthreads();
    }

#pragma unroll
    for (int mt = 0; mt < 2; mt++) {
        int row0 = m0 + wm * 32 + mt * 16 + r;
#pragma unroll
        for (int nt = 0; nt < 8; nt++) {
            int gc = n0 + wn * 64 + nt * 8 + 2 * q;
            float v0 = acc[mt][nt][0], v1 = acc[mt][nt][1];
            float v2 = acc[mt][nt][2], v3 = acc[mt][nt][3];
            if (rope) {
                int p = (gc & 63) >> 1;
                float2 cs0 = g_rope[(row0 & (S - 1)) * NPAIR + p];
                float2 cs1 = g_rope[((row0 + 8) & (S - 1)) * NPAIR + p];
                float r0 = v0 * cs0.x - v1 * cs0.y;
                float i0 = v0 * cs0.y + v1 * cs0.x;
                float r1 = v2 * cs1.x - v3 * cs1.y;
                float i1 = v2 * cs1.y + v3 * cs1.x;
                v0 = r0; v1 = i0; v2 = r1; v3 = i1;
            }
            *(float2*)&C[(size_t)row0 * ldc + gc]       = make_float2(v0, v1);
            *(float2*)&C[(size_t)(row0 + 8) * ldc + gc] = make_float2(v2, v3);
        }
    }
}

constexpr int GEMM_SMEM_SPLIT  = 4 * 128 * GP * 4;  // 73728
constexpr int GEMM_SMEM_SINGLE = 2 * 128 * GP * 4;  // 36864

__global__ void __launch_bounds__(256) qkv_kernel(const float* __restrict__ x,
                                                  const float* __restrict__ Wq,
                                                  const float* __restrict__ Wk,
                                                  const float* __restrict__ Wv) {
    extern __shared__ char smraw[];
    int bx = blockIdx.x, m0 = blockIdx.y * 128;
    const float* Wsel;
    float* Csel;
    int n0, ldc, rope;
    if (bx < 16)      { Wsel = Wq; Csel = g_Q; n0 = bx * 128;        ldc = D;   rope = 1; }
    else if (bx < 20) { Wsel = Wk; Csel = g_K; n0 = (bx - 16) * 128; ldc = Dkv; rope = 1; }
    else              { Wsel = Wv; Csel = g_V; n0 = (bx - 20) * 128; ldc = Dkv; rope = 0; }
    gemm_tile<1>(x, Wsel, Csel, n0, m0, ldc, rope, (uint32_t*)smraw);
}

__global__ void __launch_bounds__(256) out_kernel(const float* __restrict__ Wo,
                                                  float* __restrict__ out) {
    extern __shared__ char smraw[];
    gemm_tile<0>(g_Z, Wo, out, blockIdx.x * 128, blockIdx.y * 128, D, 0, (uint32_t*)smraw);
}

// ---------------------------------------------------------------- attention
// Split-tf32 Q.K^T; single-tf32 P.V (P already tf32-rounded; V rounding adds
// ~3e-4 RMS — inside budget). K/V tile prefetched into registers.
constexpr int QP = 68, PP = 36, KP = 68, VP = 72;
constexpr int ATTN_SMEM = (128 * QP + 128 * PP + 2 * 32 * KP + 32 * VP) * 4; // 79872

__global__ void __launch_bounds__(256) attn_kernel() {
    extern __shared__ char smraw[];
    float*    Qs = (float*)smraw;
    uint32_t* Ps = (uint32_t*)(smraw + 128 * QP * 4);
    uint32_t* Kh = (uint32_t*)(smraw + (128 * QP + 128 * PP) * 4);
    uint32_t* Kl = Kh + 32 * KP;
    uint32_t* Vh = Kl + 32 * KP;

    const int t = threadIdx.x, wid = t >> 5, lane = t & 31;
    const int r = lane >> 2, q = lane & 3;
    const int bh = blockIdx.y, b = bh >> 5, h = bh & 31, kvh = h >> 2;
    const int q0 = blockIdx.x * 128, w16 = wid * 16;

    const float* Qg = g_Q + (size_t)(b * S + q0) * D + h * HD;
    const float* Kg = g_K + (size_t)(b * S) * Dkv + kvh * HD;
    const float* Vg = g_V + (size_t)(b * S) * Dkv + kvh * HD;

#pragma unroll
    for (int i = 0; i < 8; i++) {
        int e = t + i * 256;
        int row = e >> 4, c4 = (e & 15) * 4;
        float4 v = *(const float4*)&Qg[(size_t)row * D + c4];
        v.x *= 0.125f; v.y *= 0.125f; v.z *= 0.125f; v.w *= 0.125f;
        *(float4*)&Qs[row * QP + c4] = v;
    }

    float oacc[8][4];
#pragma unroll
    for (int nt = 0; nt < 8; nt++)
#pragma unroll
        for (int c = 0; c < 4; c++) oacc[nt][c] = 0.f;
    float m0v = -1e30f, m1v = -1e30f, l0v = 0.f, l1v = 0.f;

    const int ldrow = t >> 4, ldc4 = (t & 15) * 4;  // rows 0..15 (+16 for i=1)

    const int nkt = q0 / 32 + 4;
    float4 pk[2], pv[2];
#pragma unroll
    for (int i = 0; i < 2; i++) {
        int row = ldrow + i * 16;
        pk[i] = *(const float4*)&Kg[(size_t)row * Dkv + ldc4];
        pv[i] = *(const float4*)&Vg[(size_t)row * Dkv + ldc4];
    }

    for (int kt = 0; kt < nkt; kt++) {
        int k0 = kt * 32;
        __syncthreads();
#pragma unroll
        for (int i = 0; i < 2; i++) {
            int row = ldrow + i * 16;
            split_store(Kh, Kl, row * KP + ldc4, pk[i]);
            tf_store(Vh, row * VP + ldc4, pv[i]);
        }
        __syncthreads();
        if (kt + 1 < nkt) {
#pragma unroll
            for (int i = 0; i < 2; i++) {
                int row = ldrow + i * 16;
                pk[i] = *(const float4*)&Kg[(size_t)(k0 + 32 + row) * Dkv + ldc4];
                pv[i] = *(const float4*)&Vg[(size_t)(k0 + 32 + row) * Dkv + ldc4];
            }
        }
        if (k0 > q0 + w16 + 15) continue;  // warp-uniform causal skip

        float sacc[4][4];
#pragma unroll
        for (int nt = 0; nt < 4; nt++)
#pragma unroll
            for (int c = 0; c < 4; c++) sacc[nt][c] = 0.f;

#pragma unroll
        for (int ks = 0; ks < 8; ks++) {
            uint32_t ah[4], al[4];
            int o = (w16 + r) * QP + ks * 8 + q;
            split1(Qs[o],              ah[0], al[0]);
            split1(Qs[o + 8 * QP],     ah[1], al[1]);
            split1(Qs[o + 4],          ah[2], al[2]);
            split1(Qs[o + 8 * QP + 4], ah[3], al[3]);
#pragma unroll
            for (int nt = 0; nt < 4; nt++) {
                int ob = (nt * 8 + r) * KP + ks * 8 + q;
                uint32_t bh0 = Kh[ob], bh1 = Kh[ob + 4];
                uint32_t bl0 = Kl[ob], bl1 = Kl[ob + 4];
                mma_tf32(sacc[nt], ah, bh0, bh1);
                mma_tf32(sacc[nt], al, bh0, bh1);
                mma_tf32(sacc[nt], ah, bl0, bl1);
            }
        }

        int qr0 = q0 + w16 + r, qr1 = qr0 + 8;
        if (k0 + 31 > q0 + w16) {
#pragma unroll
            for (int nt = 0; nt < 4; nt++) {
                int kc = k0 + nt * 8 + 2 * q;
                if (kc     > qr0) sacc[nt][0] = -1e30f;
                if (kc + 1 > qr0) sacc[nt][1] = -1e30f;
                if (kc     > qr1) sacc[nt][2] = -1e30f;
                if (kc + 1 > qr1) sacc[nt][3] = -1e30f;
            }
        }

        float rm0 = -1e30f, rm1 = -1e30f;
#pragma unroll
        for (int nt = 0; nt < 4; nt++) {
            rm0 = fmaxf(rm0, fmaxf(sacc[nt][0], sacc[nt][1]));
            rm1 = fmaxf(rm1, fmaxf(sacc[nt][2], sacc[nt][3]));
        }
        rm0 = fmaxf(rm0, __shfl_xor_sync(~0u, rm0, 1));
        rm0 = fmaxf(rm0, __shfl_xor_sync(~0u, rm0, 2));
        rm1 = fmaxf(rm1, __shfl_xor_sync(~0u, rm1, 1));
        rm1 = fmaxf(rm1, __shfl_xor_sync(~0u, rm1, 2));

        float mn0 = fmaxf(m0v, rm0), mn1 = fmaxf(m1v, rm1);
        float a0 = __expf(m0v - mn0), a1 = __expf(m1v - mn1);
        m0v = mn0; m1v = mn1;

        float ps0 = 0.f, ps1 = 0.f;
#pragma unroll
        for (int nt = 0; nt < 4; nt++) {
            float p0 = __expf(sacc[nt][0] - mn0);
            float p1 = __expf(sacc[nt][1] - mn0);
            float p2 = __expf(sacc[nt][2] - mn1);
            float p3 = __expf(sacc[nt][3] - mn1);
            ps0 += p0 + p1; ps1 += p2 + p3;
            int ob = (w16 + r) * PP + nt * 8 + 2 * q;
            Ps[ob]              = f2tf(p0);
            Ps[ob + 1]          = f2tf(p1);
            Ps[ob + 8 * PP]     = f2tf(p2);
            Ps[ob + 8 * PP + 1] = f2tf(p3);
        }
        ps0 += __shfl_xor_sync(~0u, ps0, 1); ps0 += __shfl_xor_sync(~0u, ps0, 2);
        ps1 += __shfl_xor_sync(~0u, ps1, 1); ps1 += __shfl_xor_sync(~0u, ps1, 2);
        l0v = l0v * a0 + ps0;
        l1v = l1v * a1 + ps1;
#pragma unroll
        for (int nt = 0; nt < 8; nt++) {
            oacc[nt][0] *= a0; oacc[nt][1] *= a0;
            oacc[nt][2] *= a1; oacc[nt][3] *= a1;
        }
        __syncwarp();

#pragma unroll
        for (int ks = 0; ks < 4; ks++) {
            uint32_t pa[4];
            int o = (w16 + r) * PP + ks * 8 + q;
            pa[0] = Ps[o];     pa[1] = Ps[o + 8 * PP];
            pa[2] = Ps[o + 4]; pa[3] = Ps[o + 8 * PP + 4];
#pragma unroll
            for (int nt = 0; nt < 8; nt++) {
                int ob  = (ks * 8 + q) * VP + nt * 8 + r;
                int ob2 = (ks * 8 + q + 4) * VP + nt * 8 + r;
                mma_tf32(oacc[nt], pa, Vh[ob], Vh[ob2]);
            }
        }
    }

    float inv0 = 1.f / l0v, inv1 = 1.f / l1v;
    float* Zg = g_Z + (size_t)(b * S + q0 + w16 + r) * D + h * HD;
#pragma unroll
    for (int nt = 0; nt < 8; nt++) {
        *(float2*)&Zg[nt * 8 + 2 * q] =
            make_float2(oacc[nt][0] * inv0, oacc[nt][1] * inv0);
        *(float2*)&Zg[(size_t)8 * D + nt * 8 + 2 * q] =
            make_float2(oacc[nt][2] * inv1, oacc[nt][3] * inv1);
    }
}

// ---------------------------------------------------------------- launch
extern "C" void kernel_launch(void* const* d_in, const int* in_sizes, int n_in,
                              void* d_out, int out_size) {
    const float* x  = (const float*)d_in[0];
    const float* Wq = (const float*)d_in[1];
    const float* Wk = (const float*)d_in[2];
    const float* Wv = (const float*)d_in[3];
    const float* Wo = (const float*)d_in[4];
    float* out = (float*)d_out;

    cudaFuncSetAttribute(qkv_kernel, cudaFuncAttributeMaxDynamicSharedMemorySize, GEMM_SMEM_SPLIT);
    cudaFuncSetAttribute(attn_kernel, cudaFuncAttributeMaxDynamicSharedMemorySize, ATTN_SMEM);
    cudaFuncSetAttribute(out_kernel, cudaFuncAttributeMaxDynamicSharedMemorySize, GEMM_SMEM_SINGLE);

    rope_table_kernel<<<(S * NPAIR + 255) / 256, 256>>>();
    qkv_kernel<<<dim3(24, 32), 256, GEMM_SMEM_SPLIT>>>(x, Wq, Wk, Wv);
    attn_kernel<<<dim3(16, 64), 256, ATTN_SMEM>>>();
    out_kernel<<<dim3(16, 32), 256, GEMM_SMEM_SINGLE>>>(Wo, out);
}

// round 5
// speedup vs baseline: 1.6137x; 1.3453x over previous
#include <cuda_runtime.h>
#include <cuda_bf16.h>
#include <cstdint>
#include <cstddef>

#define DEV_INLINE __device__ __forceinline__

constexpr int Bb  = 2;
constexpr int S   = 2048;
constexpr int H   = 32;
constexpr int HK  = 8;
constexpr int HD  = 64;
constexpr int D   = H * HD;    // 2048
constexpr int Dkv = HK * HD;   // 512
constexpr int M   = Bb * S;    // 4096
constexpr int NPAIR = HD / 2;  // 32

__device__ float  g_Q[M * D];
__device__ float  g_K[M * Dkv];
__device__ float  g_V[M * Dkv];
__device__ float  g_Z[M * D];
__device__ float2 g_rope[S * NPAIR];

// ---------------------------------------------------------------- numeric utils
DEV_INLINE uint32_t f2tf(float x) {
    uint32_t r;
    asm("cvt.rna.tf32.f32 %0, %1;" : "=r"(r) : "f"(x));
    return r;
}
DEV_INLINE void tf_store(uint32_t* Sh, int base, float4 v) {
    uint4 hh;
    hh.x = f2tf(v.x); hh.y = f2tf(v.y); hh.z = f2tf(v.z); hh.w = f2tf(v.w);
    *(uint4*)&Sh[base] = hh;
}
DEV_INLINE uint32_t bfpack(float a, float b) {
    __nv_bfloat162 t = __floats2bfloat162_rn(a, b);
    return *(uint32_t*)&t;
}
DEV_INLINE void bfsplit2(float x, float y, uint32_t& h, uint32_t& l) {
    __nv_bfloat16 hx = __float2bfloat16_rn(x), hy = __float2bfloat16_rn(y);
    __nv_bfloat162 hp; hp.x = hx; hp.y = hy;
    h = *(uint32_t*)&hp;
    l = bfpack(x - __bfloat162float(hx), y - __bfloat162float(hy));
}
// store float4 (4 consecutive k-values) as 2 packed hi u32 + 2 packed lo u32
DEV_INLINE void bf_split_store(uint32_t* Sh, uint32_t* Sl, int base, float4 v) {
    uint2 h, l;
    bfsplit2(v.x, v.y, h.x, l.x);
    bfsplit2(v.z, v.w, h.y, l.y);
    *(uint2*)&Sh[base] = h;
    *(uint2*)&Sl[base] = l;
}
DEV_INLINE void mma_bf16(float* c, const uint32_t* a, uint32_t b0, uint32_t b1) {
    asm volatile(
        "mma.sync.aligned.m16n8k16.row.col.f32.bf16.bf16.f32 "
        "{%0,%1,%2,%3}, {%4,%5,%6,%7}, {%8,%9}, {%0,%1,%2,%3};\n"
        : "+f"(c[0]), "+f"(c[1]), "+f"(c[2]), "+f"(c[3])
        : "r"(a[0]), "r"(a[1]), "r"(a[2]), "r"(a[3]), "r"(b0), "r"(b1));
}
DEV_INLINE void mma_tf32(float* c, const uint32_t* a, uint32_t b0, uint32_t b1) {
    asm volatile(
        "mma.sync.aligned.m16n8k8.row.col.f32.tf32.tf32.f32 "
        "{%0,%1,%2,%3}, {%4,%5,%6,%7}, {%8,%9}, {%0,%1,%2,%3};\n"
        : "+f"(c[0]), "+f"(c[1]), "+f"(c[2]), "+f"(c[3])
        : "r"(a[0]), "r"(a[1]), "r"(a[2]), "r"(a[3]), "r"(b0), "r"(b1));
}

// ---------------------------------------------------------------- rope table
__global__ void rope_table_kernel() {
    int idx = blockIdx.x * blockDim.x + threadIdx.x;
    if (idx >= S * NPAIR) return;
    int s = idx / NPAIR, p = idx % NPAIR;
    float pf   = (float)pow(10000.0, (double)(2 * p) / 64.0);
    float freq = 1.0f / pf;
    float t    = (float)s * 6.2831853071795864769f;
    float ang  = t * freq;
    double ad  = (double)ang;
    g_rope[idx] = make_float2((float)cos(ad), (float)sin(ad));
}

// ---------------------------------------------------------------- GEMM tile
// C[m0:+128, n0:+128] = A[.,2048] @ W[.,2048]^T via bf16x3 split
// (hi*hi + lo*hi + hi*lo, m16n8k16). Register-prefetch pipelined.
// Smem: packed bf16 pairs, pitch 20 u32 (16 data + 4 pad, =4 mod 32 -> conflict-free).
constexpr int GP2 = 20;

DEV_INLINE void gemm_bf16x3(const float* __restrict__ A, const float* __restrict__ W,
                            float* __restrict__ C, int n0, int m0, int ldc, int rope,
                            uint32_t* sm) {
    uint32_t* Ah = sm;
    uint32_t* Bh = Ah + 128 * GP2;
    uint32_t* Al = Bh + 128 * GP2;
    uint32_t* Bl = Al + 128 * GP2;

    const int t    = threadIdx.x;
    const int lr   = t >> 3;
    const int lc   = (t & 7) * 4;       // k-col (floats)
    const int lcu  = (t & 7) * 2;       // packed u32 col
    const int wid  = t >> 5;
    const int lane = t & 31;
    const int wm   = wid >> 1;
    const int wn   = wid & 1;
    const int r    = lane >> 2;
    const int q    = lane & 3;

    float acc[2][8][4];
#pragma unroll
    for (int a = 0; a < 2; a++)
#pragma unroll
        for (int b = 0; b < 8; b++)
#pragma unroll
            for (int c = 0; c < 4; c++) acc[a][b][c] = 0.f;

    float4 pa[4], pb[4];
#pragma unroll
    for (int i = 0; i < 4; i++) {
        int rw = lr + i * 32;
        pa[i] = *(const float4*)&A[(size_t)(m0 + rw) * 2048 + lc];
        pb[i] = *(const float4*)&W[(size_t)(n0 + rw) * 2048 + lc];
    }

    for (int kt = 0; kt < 2048; kt += 32) {
#pragma unroll
        for (int i = 0; i < 4; i++) {
            int rw = lr + i * 32;
            bf_split_store(Ah, Al, rw * GP2 + lcu, pa[i]);
            bf_split_store(Bh, Bl, rw * GP2 + lcu, pb[i]);
        }
        __syncthreads();
        if (kt + 32 < 2048) {
#pragma unroll
            for (int i = 0; i < 4; i++) {
                int rw = lr + i * 32;
                pa[i] = *(const float4*)&A[(size_t)(m0 + rw) * 2048 + kt + 32 + lc];
                pb[i] = *(const float4*)&W[(size_t)(n0 + rw) * 2048 + kt + 32 + lc];
            }
        }
#pragma unroll
        for (int ks = 0; ks < 2; ks++) {   // two k16 steps per 32-K tile
            uint32_t ah[2][4], al[2][4];
#pragma unroll
            for (int mt = 0; mt < 2; mt++) {
                int o  = (wm * 32 + mt * 16 + r) * GP2 + ks * 8 + q;
                int o8 = o + 8 * GP2;
                ah[mt][0] = Ah[o];     ah[mt][1] = Ah[o8];
                ah[mt][2] = Ah[o + 4]; ah[mt][3] = Ah[o8 + 4];
                al[mt][0] = Al[o];     al[mt][1] = Al[o8];
                al[mt][2] = Al[o + 4]; al[mt][3] = Al[o8 + 4];
            }
#pragma unroll
            for (int nt = 0; nt < 8; nt++) {
                int o = (wn * 64 + nt * 8 + r) * GP2 + ks * 8 + q;
                uint32_t bh0 = Bh[o], bh1 = Bh[o + 4];
                uint32_t bl0 = Bl[o], bl1 = Bl[o + 4];
#pragma unroll
                for (int mt = 0; mt < 2; mt++) {
                    mma_bf16(acc[mt][nt], ah[mt], bh0, bh1);
                    mma_bf16(acc[mt][nt], al[mt], bh0, bh1);
                    mma_bf16(acc[mt][nt], ah[mt], bl0, bl1);
                }
            }
        }
        __syncthreads();
    }

#pragma unroll
    for (int mt = 0; mt < 2; mt++) {
        int row0 = m0 + wm * 32 + mt * 16 + r;
#pragma unroll
        for (int nt = 0; nt < 8; nt++) {
            int gc = n0 + wn * 64 + nt * 8 + 2 * q;
            float v0 = acc[mt][nt][0], v1 = acc[mt][nt][1];
            float v2 = acc[mt][nt][2], v3 = acc[mt][nt][3];
            if (rope) {
                int p = (gc & 63) >> 1;
                float2 cs0 = g_rope[(row0 & (S - 1)) * NPAIR + p];
                float2 cs1 = g_rope[((row0 + 8) & (S - 1)) * NPAIR + p];
                float r0 = v0 * cs0.x - v1 * cs0.y;
                float i0 = v0 * cs0.y + v1 * cs0.x;
                float r1 = v2 * cs1.x - v3 * cs1.y;
                float i1 = v2 * cs1.y + v3 * cs1.x;
                v0 = r0; v1 = i0; v2 = r1; v3 = i1;
            }
            *(float2*)&C[(size_t)row0 * ldc + gc]       = make_float2(v0, v1);
            *(float2*)&C[(size_t)(row0 + 8) * ldc + gc] = make_float2(v2, v3);
        }
    }
}

constexpr int GEMM_SMEM = 4 * 128 * GP2 * 4;  // 40960

__global__ void __launch_bounds__(256) qkv_kernel(const float* __restrict__ x,
                                                  const float* __restrict__ Wq,
                                                  const float* __restrict__ Wk,
                                                  const float* __restrict__ Wv) {
    extern __shared__ char smraw[];
    int bx = blockIdx.x, m0 = blockIdx.y * 128;
    const float* Wsel;
    float* Csel;
    int n0, ldc, rope;
    if (bx < 16)      { Wsel = Wq; Csel = g_Q; n0 = bx * 128;        ldc = D;   rope = 1; }
    else if (bx < 20) { Wsel = Wk; Csel = g_K; n0 = (bx - 16) * 128; ldc = Dkv; rope = 1; }
    else              { Wsel = Wv; Csel = g_V; n0 = (bx - 20) * 128; ldc = Dkv; rope = 0; }
    gemm_bf16x3(x, Wsel, Csel, n0, m0, ldc, rope, (uint32_t*)smraw);
}

__global__ void __launch_bounds__(256) out_kernel(const float* __restrict__ Wo,
                                                  float* __restrict__ out) {
    extern __shared__ char smraw[];
    gemm_bf16x3(g_Z, Wo, out, blockIdx.x * 128, blockIdx.y * 128, D, 0, (uint32_t*)smraw);
}

// ---------------------------------------------------------------- attention
// Q.K^T: bf16x3 (Q,K pre-split into bf16 hi/lo smem). P.V: single tf32
// (P already tf32-rounded; V tf32 rounding ~3e-4 RMS, measured-safe).
constexpr int QP2 = 36, KP2 = 36, PP = 36, VP = 72;
constexpr int ATTN_SMEM =
    (2 * 128 * QP2 + 128 * PP + 2 * 32 * KP2 + 32 * VP) * 4;  // 73728

__global__ void __launch_bounds__(256) attn_kernel() {
    extern __shared__ char smraw[];
    uint32_t* Qh = (uint32_t*)smraw;
    uint32_t* Ql = Qh + 128 * QP2;
    uint32_t* Ps = Ql + 128 * QP2;
    uint32_t* Kh = Ps + 128 * PP;
    uint32_t* Kl = Kh + 32 * KP2;
    uint32_t* Vh = Kl + 32 * KP2;

    const int t = threadIdx.x, wid = t >> 5, lane = t & 31;
    const int r = lane >> 2, q = lane & 3;
    const int bh = blockIdx.y, b = bh >> 5, h = bh & 31, kvh = h >> 2;
    const int q0 = blockIdx.x * 128, w16 = wid * 16;

    const float* Qg = g_Q + (size_t)(b * S + q0) * D + h * HD;
    const float* Kg = g_K + (size_t)(b * S) * Dkv + kvh * HD;
    const float* Vg = g_V + (size_t)(b * S) * Dkv + kvh * HD;

#pragma unroll
    for (int i = 0; i < 8; i++) {
        int e = t + i * 256;
        int row = e >> 4, c4 = (e & 15) * 4;
        float4 v = *(const float4*)&Qg[(size_t)row * D + c4];
        v.x *= 0.125f; v.y *= 0.125f; v.z *= 0.125f; v.w *= 0.125f;
        bf_split_store(Qh, Ql, row * QP2 + c4 / 2, v);
    }

    float oacc[8][4];
#pragma unroll
    for (int nt = 0; nt < 8; nt++)
#pragma unroll
        for (int c = 0; c < 4; c++) oacc[nt][c] = 0.f;
    float m0v = -1e30f, m1v = -1e30f, l0v = 0.f, l1v = 0.f;

    const int ldrow = t >> 4, ldc4 = (t & 15) * 4;

    const int nkt = q0 / 32 + 4;
    float4 pk[2], pv[2];
#pragma unroll
    for (int i = 0; i < 2; i++) {
        int row = ldrow + i * 16;
        pk[i] = *(const float4*)&Kg[(size_t)row * Dkv + ldc4];
        pv[i] = *(const float4*)&Vg[(size_t)row * Dkv + ldc4];
    }

    for (int kt = 0; kt < nkt; kt++) {
        int k0 = kt * 32;
        __syncthreads();
#pragma unroll
        for (int i = 0; i < 2; i++) {
            int row = ldrow + i * 16;
            bf_split_store(Kh, Kl, row * KP2 + ldc4 / 2, pk[i]);
            tf_store(Vh, row * VP + ldc4, pv[i]);
        }
        __syncthreads();
        if (kt + 1 < nkt) {
#pragma unroll
            for (int i = 0; i < 2; i++) {
                int row = ldrow + i * 16;
                pk[i] = *(const float4*)&Kg[(size_t)(k0 + 32 + row) * Dkv + ldc4];
                pv[i] = *(const float4*)&Vg[(size_t)(k0 + 32 + row) * Dkv + ldc4];
            }
        }
        if (k0 > q0 + w16 + 15) continue;  // warp-uniform causal skip (after barriers)

        float sacc[4][4];
#pragma unroll
        for (int nt = 0; nt < 4; nt++)
#pragma unroll
            for (int c = 0; c < 4; c++) sacc[nt][c] = 0.f;

#pragma unroll
        for (int ks = 0; ks < 4; ks++) {   // 4 k16 steps over HD=64
            uint32_t ah[4], al[4];
            int o = (w16 + r) * QP2 + ks * 8 + q;
            ah[0] = Qh[o];     ah[1] = Qh[o + 8 * QP2];
            ah[2] = Qh[o + 4]; ah[3] = Qh[o + 8 * QP2 + 4];
            al[0] = Ql[o];     al[1] = Ql[o + 8 * QP2];
            al[2] = Ql[o + 4]; al[3] = Ql[o + 8 * QP2 + 4];
#pragma unroll
            for (int nt = 0; nt < 4; nt++) {
                int ob = (nt * 8 + r) * KP2 + ks * 8 + q;
                uint32_t bh0 = Kh[ob], bh1 = Kh[ob + 4];
                uint32_t bl0 = Kl[ob], bl1 = Kl[ob + 4];
                mma_bf16(sacc[nt], ah, bh0, bh1);
                mma_bf16(sacc[nt], al, bh0, bh1);
                mma_bf16(sacc[nt], ah, bl0, bl1);
            }
        }

        int qr0 = q0 + w16 + r, qr1 = qr0 + 8;
        if (k0 + 31 > q0 + w16) {
#pragma unroll
            for (int nt = 0; nt < 4; nt++) {
                int kc = k0 + nt * 8 + 2 * q;
                if (kc     > qr0) sacc[nt][0] = -1e30f;
                if (kc + 1 > qr0) sacc[nt][1] = -1e30f;
                if (kc     > qr1) sacc[nt][2] = -1e30f;
                if (kc + 1 > qr1) sacc[nt][3] = -1e30f;
            }
        }

        float rm0 = -1e30f, rm1 = -1e30f;
#pragma unroll
        for (int nt = 0; nt < 4; nt++) {
            rm0 = fmaxf(rm0, fmaxf(sacc[nt][0], sacc[nt][1]));
            rm1 = fmaxf(rm1, fmaxf(sacc[nt][2], sacc[nt][3]));
        }
        rm0 = fmaxf(rm0, __shfl_xor_sync(~0u, rm0, 1));
        rm0 = fmaxf(rm0, __shfl_xor_sync(~0u, rm0, 2));
        rm1 = fmaxf(rm1, __shfl_xor_sync(~0u, rm1, 1));
        rm1 = fmaxf(rm1, __shfl_xor_sync(~0u, rm1, 2));

        float mn0 = fmaxf(m0v, rm0), mn1 = fmaxf(m1v, rm1);
        float a0 = __expf(m0v - mn0), a1 = __expf(m1v - mn1);
        m0v = mn0; m1v = mn1;

        float ps0 = 0.f, ps1 = 0.f;
#pragma unroll
        for (int nt = 0; nt < 4; nt++) {
            float p0 = __expf(sacc[nt][0] - mn0);
            float p1 = __expf(sacc[nt][1] - mn0);
            float p2 = __expf(sacc[nt][2] - mn1);
            float p3 = __expf(sacc[nt][3] - mn1);
            ps0 += p0 + p1; ps1 += p2 + p3;
            int ob = (w16 + r) * PP + nt * 8 + 2 * q;
            Ps[ob]              = f2tf(p0);
            Ps[ob + 1]          = f2tf(p1);
            Ps[ob + 8 * PP]     = f2tf(p2);
            Ps[ob + 8 * PP + 1] = f2tf(p3);
        }
        ps0 += __shfl_xor_sync(~0u, ps0, 1); ps0 += __shfl_xor_sync(~0u, ps0, 2);
        ps1 += __shfl_xor_sync(~0u, ps1, 1); ps1 += __shfl_xor_sync(~0u, ps1, 2);
        l0v = l0v * a0 + ps0;
        l1v = l1v * a1 + ps1;
#pragma unroll
        for (int nt = 0; nt < 8; nt++) {
            oacc[nt][0] *= a0; oacc[nt][1] *= a0;
            oacc[nt][2] *= a1; oacc[nt][3] *= a1;
        }
        __syncwarp();

#pragma unroll
        for (int ks = 0; ks < 4; ks++) {
            uint32_t pa[4];
            int o = (w16 + r) * PP + ks * 8 + q;
            pa[0] = Ps[o];     pa[1] = Ps[o + 8 * PP];
            pa[2] = Ps[o + 4]; pa[3] = Ps[o + 8 * PP + 4];
#pragma unroll
            for (int nt = 0; nt < 8; nt++) {
                int ob  = (ks * 8 + q) * VP + nt * 8 + r;
                int ob2 = (ks * 8 + q + 4) * VP + nt * 8 + r;
                mma_tf32(oacc[nt], pa, Vh[ob], Vh[ob2]);
            }
        }
    }

    float inv0 = 1.f / l0v, inv1 = 1.f / l1v;
    float* Zg = g_Z + (size_t)(b * S + q0 + w16 + r) * D + h * HD;
#pragma unroll
    for (int nt = 0; nt < 8; nt++) {
        *(float2*)&Zg[nt * 8 + 2 * q] =
            make_float2(oacc[nt][0] * inv0, oacc[nt][1] * inv0);
        *(float2*)&Zg[(size_t)8 * D + nt * 8 + 2 * q] =
            make_float2(oacc[nt][2] * inv1, oacc[nt][3] * inv1);
    }
}

// ---------------------------------------------------------------- launch
extern "C" void kernel_launch(void* const* d_in, const int* in_sizes, int n_in,
                              void* d_out, int out_size) {
    const float* x  = (const float*)d_in[0];
    const float* Wq = (const float*)d_in[1];
    const float* Wk = (const float*)d_in[2];
    const float* Wv = (const float*)d_in[3];
    const float* Wo = (const float*)d_in[4];
    float* out = (float*)d_out;

    cudaFuncSetAttribute(qkv_kernel, cudaFuncAttributeMaxDynamicSharedMemorySize, GEMM_SMEM);
    cudaFuncSetAttribute(attn_kernel, cudaFuncAttributeMaxDynamicSharedMemorySize, ATTN_SMEM);
    cudaFuncSetAttribute(out_kernel, cudaFuncAttributeMaxDynamicSharedMemorySize, GEMM_SMEM);

    rope_table_kernel<<<(S * NPAIR + 255) / 256, 256>>>();
    qkv_kernel<<<dim3(24, 32), 256, GEMM_SMEM>>>(x, Wq, Wk, Wv);
    attn_kernel<<<dim3(16, 64), 256, ATTN_SMEM>>>();
    out_kernel<<<dim3(16, 32), 256, GEMM_SMEM>>>(Wo, out);
}

// round 6
// speedup vs baseline: 1.7327x; 1.0737x over previous
#include <cuda_runtime.h>
#include <cuda_bf16.h>
#include <cstdint>
#include <cstddef>

#define DEV_INLINE __device__ __forceinline__

constexpr int Bb  = 2;
constexpr int S   = 2048;
constexpr int H   = 32;
constexpr int HK  = 8;
constexpr int HD  = 64;
constexpr int D   = H * HD;    // 2048
constexpr int Dkv = HK * HD;   // 512
constexpr int M   = Bb * S;    // 4096
constexpr int NPAIR = HD / 2;  // 32

__device__ float  g_Q[M * D];
__device__ float  g_K[M * Dkv];
__device__ float  g_V[M * Dkv];
__device__ float  g_Z[M * D];
__device__ float2 g_rope[S * NPAIR];

// pre-split bf16 hi/lo arrays
__device__ __nv_bfloat16 g_xh[M * D],    g_xl[M * D];
__device__ __nv_bfloat16 g_Wqh[D * D],   g_Wql[D * D];
__device__ __nv_bfloat16 g_Wkh[Dkv * D], g_Wkl[Dkv * D];
__device__ __nv_bfloat16 g_Wvh[Dkv * D], g_Wvl[Dkv * D];
__device__ __nv_bfloat16 g_Woh[D * D],   g_Wol[D * D];
__device__ __nv_bfloat16 g_Zh[M * D],    g_Zl[M * D];

// ---------------------------------------------------------------- numeric utils
DEV_INLINE uint32_t f2tf(float x) {
    uint32_t r;
    asm("cvt.rna.tf32.f32 %0, %1;" : "=r"(r) : "f"(x));
    return r;
}
DEV_INLINE void tf_store(uint32_t* Sh, int base, float4 v) {
    uint4 hh;
    hh.x = f2tf(v.x); hh.y = f2tf(v.y); hh.z = f2tf(v.z); hh.w = f2tf(v.w);
    *(uint4*)&Sh[base] = hh;
}
DEV_INLINE uint32_t bfpack(float a, float b) {
    __nv_bfloat162 t = __floats2bfloat162_rn(a, b);
    return *(uint32_t*)&t;
}
DEV_INLINE void bfsplit2(float x, float y, uint32_t& h, uint32_t& l) {
    __nv_bfloat16 hx = __float2bfloat16_rn(x), hy = __float2bfloat16_rn(y);
    __nv_bfloat162 hp; hp.x = hx; hp.y = hy;
    h = *(uint32_t*)&hp;
    l = bfpack(x - __bfloat162float(hx), y - __bfloat162float(hy));
}
DEV_INLINE void bf_split_store(uint32_t* Sh, uint32_t* Sl, int base, float4 v) {
    uint2 h, l;
    bfsplit2(v.x, v.y, h.x, l.x);
    bfsplit2(v.z, v.w, h.y, l.y);
    *(uint2*)&Sh[base] = h;
    *(uint2*)&Sl[base] = l;
}
DEV_INLINE void mma_bf16(float* c, const uint32_t* a, uint32_t b0, uint32_t b1) {
    asm volatile(
        "mma.sync.aligned.m16n8k16.row.col.f32.bf16.bf16.f32 "
        "{%0,%1,%2,%3}, {%4,%5,%6,%7}, {%8,%9}, {%0,%1,%2,%3};\n"
        : "+f"(c[0]), "+f"(c[1]), "+f"(c[2]), "+f"(c[3])
        : "r"(a[0]), "r"(a[1]), "r"(a[2]), "r"(a[3]), "r"(b0), "r"(b1));
}
DEV_INLINE void mma_tf32(float* c, const uint32_t* a, uint32_t b0, uint32_t b1) {
    asm volatile(
        "mma.sync.aligned.m16n8k8.row.col.f32.tf32.tf32.f32 "
        "{%0,%1,%2,%3}, {%4,%5,%6,%7}, {%8,%9}, {%0,%1,%2,%3};\n"
        : "+f"(c[0]), "+f"(c[1]), "+f"(c[2]), "+f"(c[3])
        : "r"(a[0]), "r"(a[1]), "r"(a[2]), "r"(a[3]), "r"(b0), "r"(b1));
}
DEV_INLINE uint32_t smem_u32(const void* p) {
    uint32_t a;
    asm("{ .reg .u64 tmp; cvta.to.shared.u64 tmp, %1; cvt.u32.u64 %0, tmp; }"
        : "=r"(a) : "l"(p));
    return a;
}
DEV_INLINE void cp_async16(uint32_t dst, const void* src) {
    asm volatile("cp.async.cg.shared.global [%0], [%1], 16;" :: "r"(dst), "l"(src));
}
#define CP_COMMIT() asm volatile("cp.async.commit_group;" ::: "memory")
#define CP_WAIT(n)  asm volatile("cp.async.wait_group %0;" :: "n"(n) : "memory")
DEV_INLINE void ldsm_x4(uint32_t* r, uint32_t addr) {
    asm volatile("ldmatrix.sync.aligned.m8n8.x4.shared.b16 {%0,%1,%2,%3}, [%4];"
                 : "=r"(r[0]), "=r"(r[1]), "=r"(r[2]), "=r"(r[3]) : "r"(addr));
}

// ---------------------------------------------------------------- rope table
__global__ void rope_table_kernel() {
    int idx = blockIdx.x * blockDim.x + threadIdx.x;
    if (idx >= S * NPAIR) return;
    int s = idx / NPAIR, p = idx % NPAIR;
    float pf   = (float)pow(10000.0, (double)(2 * p) / 64.0);
    float freq = 1.0f / pf;
    float t    = (float)s * 6.2831853071795864769f;
    float ang  = t * freq;
    double ad  = (double)ang;
    g_rope[idx] = make_float2((float)cos(ad), (float)sin(ad));
}

// ---------------------------------------------------------------- split kernels
DEV_INLINE void split_elem4(const float* __restrict__ in, __nv_bfloat16* __restrict__ h,
                            __nv_bfloat16* __restrict__ l, int i) {
    float4 v = *(const float4*)&in[i];
    uint2 hh, ll;
    bfsplit2(v.x, v.y, hh.x, ll.x);
    bfsplit2(v.z, v.w, hh.y, ll.y);
    *(uint2*)&h[i] = hh;
    *(uint2*)&l[i] = ll;
}

__global__ void split_inputs_kernel(const float* __restrict__ x,  const float* __restrict__ Wq,
                                    const float* __restrict__ Wk, const float* __restrict__ Wv,
                                    const float* __restrict__ Wo) {
    int i = (blockIdx.x * blockDim.x + threadIdx.x) * 4;
    switch (blockIdx.y) {
        case 0: if (i < M * D)   split_elem4(x,  g_xh,  g_xl,  i); break;
        case 1: if (i < D * D)   split_elem4(Wq, g_Wqh, g_Wql, i); break;
        case 2: if (i < Dkv * D) split_elem4(Wk, g_Wkh, g_Wkl, i); break;
        case 3: if (i < Dkv * D) split_elem4(Wv, g_Wvh, g_Wvl, i); break;
        case 4: if (i < D * D)   split_elem4(Wo, g_Woh, g_Wol, i); break;
    }
}
__global__ void split_z_kernel() {
    int i = (blockIdx.x * blockDim.x + threadIdx.x) * 4;
    if (i < M * D) split_elem4(g_Z, g_Zh, g_Zl, i);
}

// ---------------------------------------------------------------- GEMM (cp.async + ldmatrix)
// C[m0:+128, n0:+128] = A @ W^T, bf16x3 split, K=2048, Ktile=32, 2-stage pipeline.
// Smem pitch 80B per row -> conflict-free LDSM.
constexpr int SPITCH  = 80;                     // bytes per 32-bf16 row
constexpr int ARR_B   = 128 * SPITCH;           // 10240 per array
constexpr int STAGE_B = 4 * ARR_B;              // 40960 per stage
constexpr int GEMM2_SMEM = 2 * STAGE_B;         // 81920

DEV_INLINE void gemm_ldsm(const __nv_bfloat16* __restrict__ Ahg, const __nv_bfloat16* __restrict__ Alg,
                          const __nv_bfloat16* __restrict__ Bhg, const __nv_bfloat16* __restrict__ Blg,
                          float* __restrict__ C, int m0, int n0, int ldc, int rope, char* sm) {
    const int t = threadIdx.x, wid = t >> 5, lane = t & 31;
    const int wm = wid >> 1, wn = wid & 1;
    const int r = lane >> 2, q = lane & 3;
    const int g4 = lane >> 3, r8 = lane & 7;
    uint32_t sb = smem_u32(sm);

    float acc[2][8][4];
#pragma unroll
    for (int a = 0; a < 2; a++)
#pragma unroll
        for (int b = 0; b < 8; b++)
#pragma unroll
            for (int c = 0; c < 4; c++) acc[a][b][c] = 0.f;

    // stage copy: 4 arrays x 128 rows x 64B; thread t does 2 chunks/array
    auto stage_copy = [&](int kt, int s) {
        uint32_t sbase = sb + s * STAGE_B;
#pragma unroll
        for (int arr = 0; arr < 4; arr++) {
            const __nv_bfloat16* g = (arr == 0) ? Ahg : (arr == 1) ? Alg : (arr == 2) ? Bhg : Blg;
            int rowbase = (arr < 2) ? m0 : n0;
            uint32_t abase = sbase + arr * ARR_B;
#pragma unroll
            for (int i = 0; i < 2; i++) {
                int c = t + i * 256;
                int row = c >> 2, cko = c & 3;
                cp_async16(abase + row * SPITCH + cko * 16,
                           g + (size_t)(rowbase + row) * 2048 + kt * 32 + cko * 8);
            }
        }
    };

    stage_copy(0, 0);
    CP_COMMIT();

    for (int kt = 0; kt < 64; kt++) {
        int s = kt & 1;
        if (kt + 1 < 64) { stage_copy(kt + 1, s ^ 1); CP_COMMIT(); CP_WAIT(1); }
        else             { CP_WAIT(0); }
        __syncthreads();

        uint32_t ab = sb + s * STAGE_B;
#pragma unroll
        for (int ks = 0; ks < 2; ks++) {
            uint32_t ah[2][4], al[2][4];
#pragma unroll
            for (int mt = 0; mt < 2; mt++) {
                uint32_t addr = ab + (wm * 32 + mt * 16 + (g4 & 1) * 8 + r8) * SPITCH
                              + (ks * 2 + (g4 >> 1)) * 16;
                ldsm_x4(ah[mt], addr);
                ldsm_x4(al[mt], addr + ARR_B);
            }
#pragma unroll
            for (int p = 0; p < 4; p++) {
                uint32_t baddr = ab + 2 * ARR_B
                               + (wn * 64 + p * 16 + (g4 >> 1) * 8 + r8) * SPITCH
                               + (ks * 2 + (g4 & 1)) * 16;
                uint32_t bhf[4], blf[4];
                ldsm_x4(bhf, baddr);
                ldsm_x4(blf, baddr + ARR_B);
#pragma unroll
                for (int hn = 0; hn < 2; hn++) {
                    int nt = p * 2 + hn;
#pragma unroll
                    for (int mt = 0; mt < 2; mt++) {
                        mma_bf16(acc[mt][nt], ah[mt], bhf[hn * 2], bhf[hn * 2 + 1]);
                        mma_bf16(acc[mt][nt], al[mt], bhf[hn * 2], bhf[hn * 2 + 1]);
                        mma_bf16(acc[mt][nt], ah[mt], blf[hn * 2], blf[hn * 2 + 1]);
                    }
                }
            }
        }
        __syncthreads();
    }

#pragma unroll
    for (int mt = 0; mt < 2; mt++) {
        int row0 = m0 + wm * 32 + mt * 16 + r;
#pragma unroll
        for (int nt = 0; nt < 8; nt++) {
            int gc = n0 + wn * 64 + nt * 8 + 2 * q;
            float v0 = acc[mt][nt][0], v1 = acc[mt][nt][1];
            float v2 = acc[mt][nt][2], v3 = acc[mt][nt][3];
            if (rope) {
                int p = (gc & 63) >> 1;
                float2 cs0 = g_rope[(row0 & (S - 1)) * NPAIR + p];
                float2 cs1 = g_rope[((row0 + 8) & (S - 1)) * NPAIR + p];
                float r0 = v0 * cs0.x - v1 * cs0.y;
                float i0 = v0 * cs0.y + v1 * cs0.x;
                float r1 = v2 * cs1.x - v3 * cs1.y;
                float i1 = v2 * cs1.y + v3 * cs1.x;
                v0 = r0; v1 = i0; v2 = r1; v3 = i1;
            }
            *(float2*)&C[(size_t)row0 * ldc + gc]       = make_float2(v0, v1);
            *(float2*)&C[(size_t)(row0 + 8) * ldc + gc] = make_float2(v2, v3);
        }
    }
}

__global__ void __launch_bounds__(256, 2) qkv_kernel() {
    extern __shared__ char smraw[];
    int bx = blockIdx.x, m0 = blockIdx.y * 128;
    const __nv_bfloat16 *Wh, *Wl;
    float* Csel;
    int n0, ldc, rope;
    if (bx < 16)      { Wh = g_Wqh; Wl = g_Wql; Csel = g_Q; n0 = bx * 128;        ldc = D;   rope = 1; }
    else if (bx < 20) { Wh = g_Wkh; Wl = g_Wkl; Csel = g_K; n0 = (bx - 16) * 128; ldc = Dkv; rope = 1; }
    else              { Wh = g_Wvh; Wl = g_Wvl; Csel = g_V; n0 = (bx - 20) * 128; ldc = Dkv; rope = 0; }
    gemm_ldsm(g_xh, g_xl, Wh, Wl, Csel, m0, n0, ldc, rope, smraw);
}

__global__ void __launch_bounds__(256, 2) out_kernel(float* __restrict__ out) {
    extern __shared__ char smraw[];
    gemm_ldsm(g_Zh, g_Zl, g_Woh, g_Wol, out, blockIdx.y * 128, blockIdx.x * 128, D, 0, smraw);
}

// ---------------------------------------------------------------- attention (unchanged R5)
constexpr int QP2 = 36, KP2 = 36, PP = 36, VP = 72;
constexpr int ATTN_SMEM =
    (2 * 128 * QP2 + 128 * PP + 2 * 32 * KP2 + 32 * VP) * 4;  // 73728

__global__ void __launch_bounds__(256) attn_kernel() {
    extern __shared__ char smraw[];
    uint32_t* Qh = (uint32_t*)smraw;
    uint32_t* Ql = Qh + 128 * QP2;
    uint32_t* Ps = Ql + 128 * QP2;
    uint32_t* Kh = Ps + 128 * PP;
    uint32_t* Kl = Kh + 32 * KP2;
    uint32_t* Vh = Kl + 32 * KP2;

    const int t = threadIdx.x, wid = t >> 5, lane = t & 31;
    const int r = lane >> 2, q = lane & 3;
    const int bh = blockIdx.y, b = bh >> 5, h = bh & 31, kvh = h >> 2;
    const int q0 = blockIdx.x * 128, w16 = wid * 16;

    const float* Qg = g_Q + (size_t)(b * S + q0) * D + h * HD;
    const float* Kg = g_K + (size_t)(b * S) * Dkv + kvh * HD;
    const float* Vg = g_V + (size_t)(b * S) * Dkv + kvh * HD;

#pragma unroll
    for (int i = 0; i < 8; i++) {
        int e = t + i * 256;
        int row = e >> 4, c4 = (e & 15) * 4;
        float4 v = *(const float4*)&Qg[(size_t)row * D + c4];
        v.x *= 0.125f; v.y *= 0.125f; v.z *= 0.125f; v.w *= 0.125f;
        bf_split_store(Qh, Ql, row * QP2 + c4 / 2, v);
    }

    float oacc[8][4];
#pragma unroll
    for (int nt = 0; nt < 8; nt++)
#pragma unroll
        for (int c = 0; c < 4; c++) oacc[nt][c] = 0.f;
    float m0v = -1e30f, m1v = -1e30f, l0v = 0.f, l1v = 0.f;

    const int ldrow = t >> 4, ldc4 = (t & 15) * 4;

    const int nkt = q0 / 32 + 4;
    float4 pk[2], pv[2];
#pragma unroll
    for (int i = 0; i < 2; i++) {
        int row = ldrow + i * 16;
        pk[i] = *(const float4*)&Kg[(size_t)row * Dkv + ldc4];
        pv[i] = *(const float4*)&Vg[(size_t)row * Dkv + ldc4];
    }

    for (int kt = 0; kt < nkt; kt++) {
        int k0 = kt * 32;
        __syncthreads();
#pragma unroll
        for (int i = 0; i < 2; i++) {
            int row = ldrow + i * 16;
            bf_split_store(Kh, Kl, row * KP2 + ldc4 / 2, pk[i]);
            tf_store(Vh, row * VP + ldc4, pv[i]);
        }
        __syncthreads();
        if (kt + 1 < nkt) {
#pragma unroll
            for (int i = 0; i < 2; i++) {
                int row = ldrow + i * 16;
                pk[i] = *(const float4*)&Kg[(size_t)(k0 + 32 + row) * Dkv + ldc4];
                pv[i] = *(const float4*)&Vg[(size_t)(k0 + 32 + row) * Dkv + ldc4];
            }
        }
        if (k0 > q0 + w16 + 15) continue;

        float sacc[4][4];
#pragma unroll
        for (int nt = 0; nt < 4; nt++)
#pragma unroll
            for (int c = 0; c < 4; c++) sacc[nt][c] = 0.f;

#pragma unroll
        for (int ks = 0; ks < 4; ks++) {
            uint32_t ah[4], al[4];
            int o = (w16 + r) * QP2 + ks * 8 + q;
            ah[0] = Qh[o];     ah[1] = Qh[o + 8 * QP2];
            ah[2] = Qh[o + 4]; ah[3] = Qh[o + 8 * QP2 + 4];
            al[0] = Ql[o];     al[1] = Ql[o + 8 * QP2];
            al[2] = Ql[o + 4]; al[3] = Ql[o + 8 * QP2 + 4];
#pragma unroll
            for (int nt = 0; nt < 4; nt++) {
                int ob = (nt * 8 + r) * KP2 + ks * 8 + q;
                uint32_t bh0 = Kh[ob], bh1 = Kh[ob + 4];
                uint32_t bl0 = Kl[ob], bl1 = Kl[ob + 4];
                mma_bf16(sacc[nt], ah, bh0, bh1);
                mma_bf16(sacc[nt], al, bh0, bh1);
                mma_bf16(sacc[nt], ah, bl0, bl1);
            }
        }

        int qr0 = q0 + w16 + r, qr1 = qr0 + 8;
        if (k0 + 31 > q0 + w16) {
#pragma unroll
            for (int nt = 0; nt < 4; nt++) {
                int kc = k0 + nt * 8 + 2 * q;
                if (kc     > qr0) sacc[nt][0] = -1e30f;
                if (kc + 1 > qr0) sacc[nt][1] = -1e30f;
                if (kc     > qr1) sacc[nt][2] = -1e30f;
                if (kc + 1 > qr1) sacc[nt][3] = -1e30f;
            }
        }

        float rm0 = -1e30f, rm1 = -1e30f;
#pragma unroll
        for (int nt = 0; nt < 4; nt++) {
            rm0 = fmaxf(rm0, fmaxf(sacc[nt][0], sacc[nt][1]));
            rm1 = fmaxf(rm1, fmaxf(sacc[nt][2], sacc[nt][3]));
        }
        rm0 = fmaxf(rm0, __shfl_xor_sync(~0u, rm0, 1));
        rm0 = fmaxf(rm0, __shfl_xor_sync(~0u, rm0, 2));
        rm1 = fmaxf(rm1, __shfl_xor_sync(~0u, rm1, 1));
        rm1 = fmaxf(rm1, __shfl_xor_sync(~0u, rm1, 2));

        float mn0 = fmaxf(m0v, rm0), mn1 = fmaxf(m1v, rm1);
        float a0 = __expf(m0v - mn0), a1 = __expf(m1v - mn1);
        m0v = mn0; m1v = mn1;

        float ps0 = 0.f, ps1 = 0.f;
#pragma unroll
        for (int nt = 0; nt < 4; nt++) {
            float p0 = __expf(sacc[nt][0] - mn0);
            float p1 = __expf(sacc[nt][1] - mn0);
            float p2 = __expf(sacc[nt][2] - mn1);
            float p3 = __expf(sacc[nt][3] - mn1);
            ps0 += p0 + p1; ps1 += p2 + p3;
            int ob = (w16 + r) * PP + nt * 8 + 2 * q;
            Ps[ob]              = f2tf(p0);
            Ps[ob + 1]          = f2tf(p1);
            Ps[ob + 8 * PP]     = f2tf(p2);
            Ps[ob + 8 * PP + 1] = f2tf(p3);
        }
        ps0 += __shfl_xor_sync(~0u, ps0, 1); ps0 += __shfl_xor_sync(~0u, ps0, 2);
        ps1 += __shfl_xor_sync(~0u, ps1, 1); ps1 += __shfl_xor_sync(~0u, ps1, 2);
        l0v = l0v * a0 + ps0;
        l1v = l1v * a1 + ps1;
#pragma unroll
        for (int nt = 0; nt < 8; nt++) {
            oacc[nt][0] *= a0; oacc[nt][1] *= a0;
            oacc[nt][2] *= a1; oacc[nt][3] *= a1;
        }
        __syncwarp();

#pragma unroll
        for (int ks = 0; ks < 4; ks++) {
            uint32_t pa[4];
            int o = (w16 + r) * PP + ks * 8 + q;
            pa[0] = Ps[o];     pa[1] = Ps[o + 8 * PP];
            pa[2] = Ps[o + 4]; pa[3] = Ps[o + 8 * PP + 4];
#pragma unroll
            for (int nt = 0; nt < 8; nt++) {
                int ob  = (ks * 8 + q) * VP + nt * 8 + r;
                int ob2 = (ks * 8 + q + 4) * VP + nt * 8 + r;
                mma_tf32(oacc[nt], pa, Vh[ob], Vh[ob2]);
            }
        }
    }

    float inv0 = 1.f / l0v, inv1 = 1.f / l1v;
    float* Zg = g_Z + (size_t)(b * S + q0 + w16 + r) * D + h * HD;
#pragma unroll
    for (int nt = 0; nt < 8; nt++) {
        *(float2*)&Zg[nt * 8 + 2 * q] =
            make_float2(oacc[nt][0] * inv0, oacc[nt][1] * inv0);
        *(float2*)&Zg[(size_t)8 * D + nt * 8 + 2 * q] =
            make_float2(oacc[nt][2] * inv1, oacc[nt][3] * inv1);
    }
}

// ---------------------------------------------------------------- launch
extern "C" void kernel_launch(void* const* d_in, const int* in_sizes, int n_in,
                              void* d_out, int out_size) {
    const float* x  = (const float*)d_in[0];
    const float* Wq = (const float*)d_in[1];
    const float* Wk = (const float*)d_in[2];
    const float* Wv = (const float*)d_in[3];
    const float* Wo = (const float*)d_in[4];
    float* out = (float*)d_out;

    cudaFuncSetAttribute(qkv_kernel, cudaFuncAttributeMaxDynamicSharedMemorySize, GEMM2_SMEM);
    cudaFuncSetAttribute(attn_kernel, cudaFuncAttributeMaxDynamicSharedMemorySize, ATTN_SMEM);
    cudaFuncSetAttribute(out_kernel, cudaFuncAttributeMaxDynamicSharedMemorySize, GEMM2_SMEM);

    rope_table_kernel<<<(S * NPAIR + 255) / 256, 256>>>();
    split_inputs_kernel<<<dim3((M * D / 4 + 255) / 256, 5), 256>>>(x, Wq, Wk, Wv, Wo);
    qkv_kernel<<<dim3(24, 32), 256, GEMM2_SMEM>>>();
    attn_kernel<<<dim3(16, 64), 256, ATTN_SMEM>>>();
    split_z_kernel<<<(M * D / 4 + 255) / 256, 256>>>();
    out_kernel<<<dim3(16, 32), 256, GEMM2_SMEM>>>(out);
}

// round 7
// speedup vs baseline: 1.7728x; 1.0232x over previous
#include <cuda_runtime.h>
#include <cuda_bf16.h>
#include <cstdint>
#include <cstddef>

#define DEV_INLINE __device__ __forceinline__

constexpr int Bb  = 2;
constexpr int S   = 2048;
constexpr int H   = 32;
constexpr int HK  = 8;
constexpr int HD  = 64;
constexpr int D   = H * HD;    // 2048
constexpr int Dkv = HK * HD;   // 512
constexpr int M   = Bb * S;    // 4096
constexpr int NPAIR = HD / 2;  // 32

__device__ float  g_Q[M * D];
__device__ float  g_K[M * Dkv];
__device__ float  g_V[M * Dkv];
__device__ float  g_Z[M * D];
__device__ float2 g_rope[S * NPAIR];

// pre-split bf16 hi/lo arrays
__device__ __nv_bfloat16 g_xh[M * D],    g_xl[M * D];
__device__ __nv_bfloat16 g_Wqh[D * D],   g_Wql[D * D];
__device__ __nv_bfloat16 g_Wkh[Dkv * D], g_Wkl[Dkv * D];
__device__ __nv_bfloat16 g_Wvh[Dkv * D], g_Wvl[Dkv * D];
__device__ __nv_bfloat16 g_Woh[D * D],   g_Wol[D * D];
__device__ __nv_bfloat16 g_Zh[M * D],    g_Zl[M * D];

// ---------------------------------------------------------------- numeric utils
DEV_INLINE uint32_t f2tf(float x) {
    uint32_t r;
    asm("cvt.rna.tf32.f32 %0, %1;" : "=r"(r) : "f"(x));
    return r;
}
DEV_INLINE void tf_store(uint32_t* Sh, int base, float4 v) {
    uint4 hh;
    hh.x = f2tf(v.x); hh.y = f2tf(v.y); hh.z = f2tf(v.z); hh.w = f2tf(v.w);
    *(uint4*)&Sh[base] = hh;
}
DEV_INLINE uint32_t bfpack(float a, float b) {
    __nv_bfloat162 t = __floats2bfloat162_rn(a, b);
    return *(uint32_t*)&t;
}
DEV_INLINE void bfsplit2(float x, float y, uint32_t& h, uint32_t& l) {
    __nv_bfloat16 hx = __float2bfloat16_rn(x), hy = __float2bfloat16_rn(y);
    __nv_bfloat162 hp; hp.x = hx; hp.y = hy;
    h = *(uint32_t*)&hp;
    l = bfpack(x - __bfloat162float(hx), y - __bfloat162float(hy));
}
DEV_INLINE void bf_split_store(uint32_t* Sh, uint32_t* Sl, int base, float4 v) {
    uint2 h, l;
    bfsplit2(v.x, v.y, h.x, l.x);
    bfsplit2(v.z, v.w, h.y, l.y);
    *(uint2*)&Sh[base] = h;
    *(uint2*)&Sl[base] = l;
}
DEV_INLINE void mma_bf16(float* c, const uint32_t* a, uint32_t b0, uint32_t b1) {
    asm volatile(
        "mma.sync.aligned.m16n8k16.row.col.f32.bf16.bf16.f32 "
        "{%0,%1,%2,%3}, {%4,%5,%6,%7}, {%8,%9}, {%0,%1,%2,%3};\n"
        : "+f"(c[0]), "+f"(c[1]), "+f"(c[2]), "+f"(c[3])
        : "r"(a[0]), "r"(a[1]), "r"(a[2]), "r"(a[3]), "r"(b0), "r"(b1));
}
DEV_INLINE void mma_tf32(float* c, const uint32_t* a, uint32_t b0, uint32_t b1) {
    asm volatile(
        "mma.sync.aligned.m16n8k8.row.col.f32.tf32.tf32.f32 "
        "{%0,%1,%2,%3}, {%4,%5,%6,%7}, {%8,%9}, {%0,%1,%2,%3};\n"
        : "+f"(c[0]), "+f"(c[1]), "+f"(c[2]), "+f"(c[3])
        : "r"(a[0]), "r"(a[1]), "r"(a[2]), "r"(a[3]), "r"(b0), "r"(b1));
}
DEV_INLINE uint32_t smem_u32(const void* p) {
    uint32_t a;
    asm("{ .reg .u64 tmp; cvta.to.shared.u64 tmp, %1; cvt.u32.u64 %0, tmp; }"
        : "=r"(a) : "l"(p));
    return a;
}
DEV_INLINE void cp_async16(uint32_t dst, const void* src) {
    asm volatile("cp.async.cg.shared.global [%0], [%1], 16;" :: "r"(dst), "l"(src));
}
#define CP_COMMIT() asm volatile("cp.async.commit_group;" ::: "memory")
#define CP_WAIT(n)  asm volatile("cp.async.wait_group %0;" :: "n"(n) : "memory")
DEV_INLINE void ldsm_x4(uint32_t* r, uint32_t addr) {
    asm volatile("ldmatrix.sync.aligned.m8n8.x4.shared.b16 {%0,%1,%2,%3}, [%4];"
                 : "=r"(r[0]), "=r"(r[1]), "=r"(r[2]), "=r"(r[3]) : "r"(addr));
}

// ---------------------------------------------------------------- rope table
__global__ void rope_table_kernel() {
    int idx = blockIdx.x * blockDim.x + threadIdx.x;
    if (idx >= S * NPAIR) return;
    int s = idx / NPAIR, p = idx % NPAIR;
    float pf   = (float)pow(10000.0, (double)(2 * p) / 64.0);
    float freq = 1.0f / pf;
    float t    = (float)s * 6.2831853071795864769f;
    float ang  = t * freq;
    double ad  = (double)ang;
    g_rope[idx] = make_float2((float)cos(ad), (float)sin(ad));
}

// ---------------------------------------------------------------- split kernels
DEV_INLINE void split_elem4(const float* __restrict__ in, __nv_bfloat16* __restrict__ h,
                            __nv_bfloat16* __restrict__ l, int i) {
    float4 v = *(const float4*)&in[i];
    uint2 hh, ll;
    bfsplit2(v.x, v.y, hh.x, ll.x);
    bfsplit2(v.z, v.w, hh.y, ll.y);
    *(uint2*)&h[i] = hh;
    *(uint2*)&l[i] = ll;
}

__global__ void split_inputs_kernel(const float* __restrict__ x,  const float* __restrict__ Wq,
                                    const float* __restrict__ Wk, const float* __restrict__ Wv,
                                    const float* __restrict__ Wo) {
    int i = (blockIdx.x * blockDim.x + threadIdx.x) * 4;
    switch (blockIdx.y) {
        case 0: if (i < M * D)   split_elem4(x,  g_xh,  g_xl,  i); break;
        case 1: if (i < D * D)   split_elem4(Wq, g_Wqh, g_Wql, i); break;
        case 2: if (i < Dkv * D) split_elem4(Wk, g_Wkh, g_Wkl, i); break;
        case 3: if (i < Dkv * D) split_elem4(Wv, g_Wvh, g_Wvl, i); break;
        case 4: if (i < D * D)   split_elem4(Wo, g_Woh, g_Wol, i); break;
    }
}
__global__ void split_z_kernel() {
    int i = (blockIdx.x * blockDim.x + threadIdx.x) * 4;
    if (i < M * D) split_elem4(g_Z, g_Zh, g_Zl, i);
}

// ---------------------------------------------------------------- GEMM (cp.async + ldmatrix)
constexpr int SPITCH  = 80;                     // bytes per 32-bf16 row
constexpr int ARR_B   = 128 * SPITCH;           // 10240 per array
constexpr int STAGE_B = 4 * ARR_B;              // 40960 per stage
constexpr int GEMM2_SMEM = 2 * STAGE_B;         // 81920

DEV_INLINE void gemm_ldsm(const __nv_bfloat16* __restrict__ Ahg, const __nv_bfloat16* __restrict__ Alg,
                          const __nv_bfloat16* __restrict__ Bhg, const __nv_bfloat16* __restrict__ Blg,
                          float* __restrict__ C, int m0, int n0, int ldc, int rope, char* sm) {
    const int t = threadIdx.x, wid = t >> 5, lane = t & 31;
    const int wm = wid >> 1, wn = wid & 1;
    const int r = lane >> 2, q = lane & 3;
    const int g4 = lane >> 3, r8 = lane & 7;
    uint32_t sb = smem_u32(sm);

    float acc[2][8][4];
#pragma unroll
    for (int a = 0; a < 2; a++)
#pragma unroll
        for (int b = 0; b < 8; b++)
#pragma unroll
            for (int c = 0; c < 4; c++) acc[a][b][c] = 0.f;

    auto stage_copy = [&](int kt, int s) {
        uint32_t sbase = sb + s * STAGE_B;
#pragma unroll
        for (int arr = 0; arr < 4; arr++) {
            const __nv_bfloat16* g = (arr == 0) ? Ahg : (arr == 1) ? Alg : (arr == 2) ? Bhg : Blg;
            int rowbase = (arr < 2) ? m0 : n0;
            uint32_t abase = sbase + arr * ARR_B;
#pragma unroll
            for (int i = 0; i < 2; i++) {
                int c = t + i * 256;
                int row = c >> 2, cko = c & 3;
                cp_async16(abase + row * SPITCH + cko * 16,
                           g + (size_t)(rowbase + row) * 2048 + kt * 32 + cko * 8);
            }
        }
    };

    stage_copy(0, 0);
    CP_COMMIT();

    for (int kt = 0; kt < 64; kt++) {
        int s = kt & 1;
        if (kt + 1 < 64) { stage_copy(kt + 1, s ^ 1); CP_COMMIT(); CP_WAIT(1); }
        else             { CP_WAIT(0); }
        __syncthreads();

        uint32_t ab = sb + s * STAGE_B;
#pragma unroll
        for (int ks = 0; ks < 2; ks++) {
            uint32_t ah[2][4], al[2][4];
#pragma unroll
            for (int mt = 0; mt < 2; mt++) {
                uint32_t addr = ab + (wm * 32 + mt * 16 + (g4 & 1) * 8 + r8) * SPITCH
                              + (ks * 2 + (g4 >> 1)) * 16;
                ldsm_x4(ah[mt], addr);
                ldsm_x4(al[mt], addr + ARR_B);
            }
#pragma unroll
            for (int p = 0; p < 4; p++) {
                uint32_t baddr = ab + 2 * ARR_B
                               + (wn * 64 + p * 16 + (g4 >> 1) * 8 + r8) * SPITCH
                               + (ks * 2 + (g4 & 1)) * 16;
                uint32_t bhf[4], blf[4];
                ldsm_x4(bhf, baddr);
                ldsm_x4(blf, baddr + ARR_B);
#pragma unroll
                for (int hn = 0; hn < 2; hn++) {
                    int nt = p * 2 + hn;
#pragma unroll
                    for (int mt = 0; mt < 2; mt++) {
                        mma_bf16(acc[mt][nt], ah[mt], bhf[hn * 2], bhf[hn * 2 + 1]);
                        mma_bf16(acc[mt][nt], al[mt], bhf[hn * 2], bhf[hn * 2 + 1]);
                        mma_bf16(acc[mt][nt], ah[mt], blf[hn * 2], blf[hn * 2 + 1]);
                    }
                }
            }
        }
        __syncthreads();
    }

#pragma unroll
    for (int mt = 0; mt < 2; mt++) {
        int row0 = m0 + wm * 32 + mt * 16 + r;
#pragma unroll
        for (int nt = 0; nt < 8; nt++) {
            int gc = n0 + wn * 64 + nt * 8 + 2 * q;
            float v0 = acc[mt][nt][0], v1 = acc[mt][nt][1];
            float v2 = acc[mt][nt][2], v3 = acc[mt][nt][3];
            if (rope) {
                int p = (gc & 63) >> 1;
                float2 cs0 = g_rope[(row0 & (S - 1)) * NPAIR + p];
                float2 cs1 = g_rope[((row0 + 8) & (S - 1)) * NPAIR + p];
                float r0 = v0 * cs0.x - v1 * cs0.y;
                float i0 = v0 * cs0.y + v1 * cs0.x;
                float r1 = v2 * cs1.x - v3 * cs1.y;
                float i1 = v2 * cs1.y + v3 * cs1.x;
                v0 = r0; v1 = i0; v2 = r1; v3 = i1;
            }
            *(float2*)&C[(size_t)row0 * ldc + gc]       = make_float2(v0, v1);
            *(float2*)&C[(size_t)(row0 + 8) * ldc + gc] = make_float2(v2, v3);
        }
    }
}

__global__ void __launch_bounds__(256, 2) qkv_kernel() {
    extern __shared__ char smraw[];
    int bx = blockIdx.x, m0 = blockIdx.y * 128;
    const __nv_bfloat16 *Wh, *Wl;
    float* Csel;
    int n0, ldc, rope;
    if (bx < 16)      { Wh = g_Wqh; Wl = g_Wql; Csel = g_Q; n0 = bx * 128;        ldc = D;   rope = 1; }
    else if (bx < 20) { Wh = g_Wkh; Wl = g_Wkl; Csel = g_K; n0 = (bx - 16) * 128; ldc = Dkv; rope = 1; }
    else              { Wh = g_Wvh; Wl = g_Wvl; Csel = g_V; n0 = (bx - 20) * 128; ldc = Dkv; rope = 0; }
    gemm_ldsm(g_xh, g_xl, Wh, Wl, Csel, m0, n0, ldc, rope, smraw);
}

__global__ void __launch_bounds__(256, 2) out_kernel(float* __restrict__ out) {
    extern __shared__ char smraw[];
    gemm_ldsm(g_Zh, g_Zl, g_Woh, g_Wol, out, blockIdx.y * 128, blockIdx.x * 128, D, 0, smraw);
}

// ---------------------------------------------------------------- attention
// Q.K^T bf16x3 fed by ldmatrix (pitch 144B = conflict-free); P.V tf32 scalar.
constexpr int QP2 = 36, KP2 = 36, PP = 36, VP = 72;
constexpr int QROWB = QP2 * 4;   // 144 bytes per Q/K row
constexpr int ATTN_SMEM =
    (2 * 128 * QP2 + 128 * PP + 2 * 32 * KP2 + 32 * VP) * 4;  // 73728

__global__ void __launch_bounds__(256) attn_kernel() {
    extern __shared__ char smraw[];
    uint32_t* Qh = (uint32_t*)smraw;
    uint32_t* Ql = Qh + 128 * QP2;
    uint32_t* Ps = Ql + 128 * QP2;
    uint32_t* Kh = Ps + 128 * PP;
    uint32_t* Kl = Kh + 32 * KP2;
    uint32_t* Vh = Kl + 32 * KP2;

    const int t = threadIdx.x, wid = t >> 5, lane = t & 31;
    const int r = lane >> 2, q = lane & 3;
    const int g4 = lane >> 3, r8 = lane & 7;
    const int bh = blockIdx.y, b = bh >> 5, h = bh & 31, kvh = h >> 2;
    const int q0 = blockIdx.x * 128, w16 = wid * 16;

    const uint32_t qhb = smem_u32(Qh), qlb = smem_u32(Ql);
    const uint32_t khb = smem_u32(Kh), klb = smem_u32(Kl);

    const float* Qg = g_Q + (size_t)(b * S + q0) * D + h * HD;
    const float* Kg = g_K + (size_t)(b * S) * Dkv + kvh * HD;
    const float* Vg = g_V + (size_t)(b * S) * Dkv + kvh * HD;

#pragma unroll
    for (int i = 0; i < 8; i++) {
        int e = t + i * 256;
        int row = e >> 4, c4 = (e & 15) * 4;
        float4 v = *(const float4*)&Qg[(size_t)row * D + c4];
        v.x *= 0.125f; v.y *= 0.125f; v.z *= 0.125f; v.w *= 0.125f;
        bf_split_store(Qh, Ql, row * QP2 + c4 / 2, v);
    }

    float oacc[8][4];
#pragma unroll
    for (int nt = 0; nt < 8; nt++)
#pragma unroll
        for (int c = 0; c < 4; c++) oacc[nt][c] = 0.f;
    float m0v = -1e30f, m1v = -1e30f, l0v = 0.f, l1v = 0.f;

    const int ldrow = t >> 4, ldc4 = (t & 15) * 4;

    const int nkt = q0 / 32 + 4;
    float4 pk[2], pv[2];
#pragma unroll
    for (int i = 0; i < 2; i++) {
        int row = ldrow + i * 16;
        pk[i] = *(const float4*)&Kg[(size_t)row * Dkv + ldc4];
        pv[i] = *(const float4*)&Vg[(size_t)row * Dkv + ldc4];
    }

    for (int kt = 0; kt < nkt; kt++) {
        int k0 = kt * 32;
        __syncthreads();
#pragma unroll
        for (int i = 0; i < 2; i++) {
            int row = ldrow + i * 16;
            bf_split_store(Kh, Kl, row * KP2 + ldc4 / 2, pk[i]);
            tf_store(Vh, row * VP + ldc4, pv[i]);
        }
        __syncthreads();
        if (kt + 1 < nkt) {
#pragma unroll
            for (int i = 0; i < 2; i++) {
                int row = ldrow + i * 16;
                pk[i] = *(const float4*)&Kg[(size_t)(k0 + 32 + row) * Dkv + ldc4];
                pv[i] = *(const float4*)&Vg[(size_t)(k0 + 32 + row) * Dkv + ldc4];
            }
        }
        if (k0 > q0 + w16 + 15) continue;

        float sacc[4][4];
#pragma unroll
        for (int nt = 0; nt < 4; nt++)
#pragma unroll
            for (int c = 0; c < 4; c++) sacc[nt][c] = 0.f;

#pragma unroll
        for (int ks = 0; ks < 4; ks++) {   // 4 k16 steps over HD=64
            uint32_t ah[4], al[4];
            uint32_t qoff = (uint32_t)(w16 + (g4 & 1) * 8 + r8) * QROWB
                          + (uint32_t)(ks * 2 + (g4 >> 1)) * 16;
            ldsm_x4(ah, qhb + qoff);
            ldsm_x4(al, qlb + qoff);
#pragma unroll
            for (int p = 0; p < 2; p++) {
                uint32_t koff = (uint32_t)(p * 16 + (g4 >> 1) * 8 + r8) * QROWB
                              + (uint32_t)(ks * 2 + (g4 & 1)) * 16;
                uint32_t bhf[4], blf[4];
                ldsm_x4(bhf, khb + koff);
                ldsm_x4(blf, klb + koff);
#pragma unroll
                for (int hn = 0; hn < 2; hn++) {
                    int nt = p * 2 + hn;
                    mma_bf16(sacc[nt], ah, bhf[hn * 2], bhf[hn * 2 + 1]);
                    mma_bf16(sacc[nt], al, bhf[hn * 2], bhf[hn * 2 + 1]);
                    mma_bf16(sacc[nt], ah, blf[hn * 2], blf[hn * 2 + 1]);
                }
            }
        }

        int qr0 = q0 + w16 + r, qr1 = qr0 + 8;
        if (k0 + 31 > q0 + w16) {
#pragma unroll
            for (int nt = 0; nt < 4; nt++) {
                int kc = k0 + nt * 8 + 2 * q;
                if (kc     > qr0) sacc[nt][0] = -1e30f;
                if (kc + 1 > qr0) sacc[nt][1] = -1e30f;
                if (kc     > qr1) sacc[nt][2] = -1e30f;
                if (kc + 1 > qr1) sacc[nt][3] = -1e30f;
            }
        }

        float rm0 = -1e30f, rm1 = -1e30f;
#pragma unroll
        for (int nt = 0; nt < 4; nt++) {
            rm0 = fmaxf(rm0, fmaxf(sacc[nt][0], sacc[nt][1]));
            rm1 = fmaxf(rm1, fmaxf(sacc[nt][2], sacc[nt][3]));
        }
        rm0 = fmaxf(rm0, __shfl_xor_sync(~0u, rm0, 1));
        rm0 = fmaxf(rm0, __shfl_xor_sync(~0u, rm0, 2));
        rm1 = fmaxf(rm1, __shfl_xor_sync(~0u, rm1, 1));
        rm1 = fmaxf(rm1, __shfl_xor_sync(~0u, rm1, 2));

        float mn0 = fmaxf(m0v, rm0), mn1 = fmaxf(m1v, rm1);
        float a0 = __expf(m0v - mn0), a1 = __expf(m1v - mn1);
        m0v = mn0; m1v = mn1;

        float ps0 = 0.f, ps1 = 0.f;
#pragma unroll
        for (int nt = 0; nt < 4; nt++) {
            float p0 = __expf(sacc[nt][0] - mn0);
            float p1 = __expf(sacc[nt][1] - mn0);
            float p2 = __expf(sacc[nt][2] - mn1);
            float p3 = __expf(sacc[nt][3] - mn1);
            ps0 += p0 + p1; ps1 += p2 + p3;
            int ob = (w16 + r) * PP + nt * 8 + 2 * q;
            Ps[ob]              = f2tf(p0);
            Ps[ob + 1]          = f2tf(p1);
            Ps[ob + 8 * PP]     = f2tf(p2);
            Ps[ob + 8 * PP + 1] = f2tf(p3);
        }
        ps0 += __shfl_xor_sync(~0u, ps0, 1); ps0 += __shfl_xor_sync(~0u, ps0, 2);
        ps1 += __shfl_xor_sync(~0u, ps1, 1); ps1 += __shfl_xor_sync(~0u, ps1, 2);
        l0v = l0v * a0 + ps0;
        l1v = l1v * a1 + ps1;
#pragma unroll
        for (int nt = 0; nt < 8; nt++) {
            oacc[nt][0] *= a0; oacc[nt][1] *= a0;
            oacc[nt][2] *= a1; oacc[nt][3] *= a1;
        }
        __syncwarp();

#pragma unroll
        for (int ks = 0; ks < 4; ks++) {
            uint32_t pa[4];
            int o = (w16 + r) * PP + ks * 8 + q;
            pa[0] = Ps[o];     pa[1] = Ps[o + 8 * PP];
            pa[2] = Ps[o + 4]; pa[3] = Ps[o + 8 * PP + 4];
#pragma unroll
            for (int nt = 0; nt < 8; nt++) {
                int ob  = (ks * 8 + q) * VP + nt * 8 + r;
                int ob2 = (ks * 8 + q + 4) * VP + nt * 8 + r;
                mma_tf32(oacc[nt], pa, Vh[ob], Vh[ob2]);
            }
        }
    }

    float inv0 = 1.f / l0v, inv1 = 1.f / l1v;
    float* Zg = g_Z + (size_t)(b * S + q0 + w16 + r) * D + h * HD;
#pragma unroll
    for (int nt = 0; nt < 8; nt++) {
        *(float2*)&Zg[nt * 8 + 2 * q] =
            make_float2(oacc[nt][0] * inv0, oacc[nt][1] * inv0);
        *(float2*)&Zg[(size_t)8 * D + nt * 8 + 2 * q] =
            make_float2(oacc[nt][2] * inv1, oacc[nt][3] * inv1);
    }
}

// ---------------------------------------------------------------- launch
extern "C" void kernel_launch(void* const* d_in, const int* in_sizes, int n_in,
                              void* d_out, int out_size) {
    const float* x  = (const float*)d_in[0];
    const float* Wq = (const float*)d_in[1];
    const float* Wk = (const float*)d_in[2];
    const float* Wv = (const float*)d_in[3];
    const float* Wo = (const float*)d_in[4];
    float* out = (float*)d_out;

    cudaFuncSetAttribute(qkv_kernel, cudaFuncAttributeMaxDynamicSharedMemorySize, GEMM2_SMEM);
    cudaFuncSetAttribute(attn_kernel, cudaFuncAttributeMaxDynamicSharedMemorySize, ATTN_SMEM);
    cudaFuncSetAttribute(out_kernel, cudaFuncAttributeMaxDynamicSharedMemorySize, GEMM2_SMEM);

    rope_table_kernel<<<(S * NPAIR + 255) / 256, 256>>>();
    split_inputs_kernel<<<dim3((M * D / 4 + 255) / 256, 5), 256>>>(x, Wq, Wk, Wv, Wo);
    qkv_kernel<<<dim3(24, 32), 256, GEMM2_SMEM>>>();
    attn_kernel<<<dim3(16, 64), 256, ATTN_SMEM>>>();
    split_z_kernel<<<(M * D / 4 + 255) / 256, 256>>>();
    out_kernel<<<dim3(16, 32), 256, GEMM2_SMEM>>>(out);
}